// round 10
// baseline (speedup 1.0000x reference)
#include <cuda_runtime.h>
#include <cuda_bf16.h>
#include <cstdint>
#include <math.h>

// ---------------- problem constants ----------------
#define KB_   8
#define KT_   4096
#define KD_   768
#define KH_   12
#define KHD_  64
#define KINT_ 3
#define KBT_  (KB_ * KT_)                 // 32768
#define KNELEM_ ((size_t)KBT_ * KD_)      // 25165824
#define KST_  1536                        // stored K width: [hi(768) | lo(768)]
#define KNQKV_ 2304                       // Wq|Wk|Wv stacked along N
#define WELEM_ (KD_ * KD_)

// GEMM tiling: 128x128 CTA, 64x32 warp, 3 stages -> 2 CTAs/SM, persistent
#define BM_ 128
#define BN_ 128
#define BK_ 64
#define KITERS_ 36                        // 36 chunks of 64: hh(12) + lh(12) + hl(12)
#define STAGES_ 3
#define STAGE_BYTES_ 32768u               // A 16KB + B 16KB
#define OFF_B_ 16384u
#define SMEM_BYTES_ (STAGES_ * STAGE_BYTES_)   // 98304
#define NPERSIST_ 296                     // 2 CTAs x 148 SMs

// ---------------- device scratch ----------------
__device__ __nv_bfloat16 g_a2[(size_t)KBT_ * KST_];          // split activations [hi|lo]
__device__ __nv_bfloat16 g_w2[4 * (size_t)KD_ * KST_];       // split weights [Wh|Wl] per matrix
__device__ float g_bqkv[KNQKV_];                             // concat bias q|k|v
__device__ float g_qkv[(size_t)KBT_ * KNQKV_];               // fused QKV output
__device__ float g_o[KNELEM_];

// ---------------- helpers ----------------
__device__ __forceinline__ uint32_t smem_u32(const void* p) {
    return (uint32_t)__cvta_generic_to_shared(p);
}

__device__ __forceinline__ void cp_async16(uint32_t saddr, const void* gaddr) {
    asm volatile("cp.async.cg.shared.global [%0], [%1], 16;" :: "r"(saddr), "l"(gaddr));
}
#define CP_COMMIT_()  asm volatile("cp.async.commit_group;" ::: "memory")
#define CP_WAIT_(n)   asm volatile("cp.async.wait_group %0;" :: "n"(n) : "memory")

__device__ __forceinline__ void ldsm_x4(uint32_t& r0, uint32_t& r1, uint32_t& r2, uint32_t& r3,
                                        uint32_t addr) {
    asm volatile("ldmatrix.sync.aligned.m8n8.x4.shared.b16 {%0,%1,%2,%3}, [%4];"
                 : "=r"(r0), "=r"(r1), "=r"(r2), "=r"(r3) : "r"(addr));
}

__device__ __forceinline__ void mma_bf16(float* c, const uint32_t* a, const uint32_t* b) {
    asm volatile(
        "mma.sync.aligned.m16n8k16.row.col.f32.bf16.bf16.f32 "
        "{%0,%1,%2,%3}, {%4,%5,%6,%7}, {%8,%9}, {%0,%1,%2,%3};"
        : "+f"(c[0]), "+f"(c[1]), "+f"(c[2]), "+f"(c[3])
        : "r"(a[0]), "r"(a[1]), "r"(a[2]), "r"(a[3]), "r"(b[0]), "r"(b[1]));
}

// ---------------- kernel 1: transpose + split weights, concat bias ----------------
__global__ __launch_bounds__(256) void prep_weights_kernel(
    const float* __restrict__ Wq, const float* __restrict__ Wk,
    const float* __restrict__ Wv, const float* __restrict__ Wo,
    const float* __restrict__ bq, const float* __restrict__ bk,
    const float* __restrict__ bv) {
    int idx = blockIdx.x * 256 + threadIdx.x;       // over D*D
    int n = idx / KD_;
    int k = idx - n * KD_;
    const float* Ws[4] = {Wq, Wk, Wv, Wo};
#pragma unroll
    for (int w = 0; w < 4; w++) {
        float val = Ws[w][(size_t)k * KD_ + n];     // W[k][n] -> B[n][k]
        __nv_bfloat16 hi = __float2bfloat16(val);
        __nv_bfloat16 lo = __float2bfloat16(val - __bfloat162float(hi));
        size_t base = (size_t)w * KD_ * KST_ + (size_t)n * KST_;
        g_w2[base + k]       = hi;
        g_w2[base + 768 + k] = lo;
    }
    if (idx < KNQKV_) {
        g_bqkv[idx] = (idx < 768) ? bq[idx] : (idx < 1536) ? bk[idx - 768] : bv[idx - 1536];
    }
}

// ---------------- kernel 2: split x -> [hi | lo] rows of 1536 (float4) ----------------
__global__ __launch_bounds__(256) void split_x_kernel(const float* __restrict__ x) {
    long long gid = (long long)blockIdx.x * 256 + threadIdx.x;   // over KNELEM/4
    long long i = gid * 4;
    int row = (int)(i / KD_);
    int col = (int)(i - (long long)row * KD_);
    float4 v = *reinterpret_cast<const float4*>(x + i);
    __nv_bfloat16 h0 = __float2bfloat16(v.x), h1 = __float2bfloat16(v.y);
    __nv_bfloat16 h2 = __float2bfloat16(v.z), h3 = __float2bfloat16(v.w);
    __nv_bfloat16 l0 = __float2bfloat16(v.x - __bfloat162float(h0));
    __nv_bfloat16 l1 = __float2bfloat16(v.y - __bfloat162float(h1));
    __nv_bfloat16 l2 = __float2bfloat16(v.z - __bfloat162float(h2));
    __nv_bfloat16 l3 = __float2bfloat16(v.w - __bfloat162float(h3));
    uint2 hh, ll;
    hh.x = ((uint32_t)__bfloat16_as_ushort(h1) << 16) | __bfloat16_as_ushort(h0);
    hh.y = ((uint32_t)__bfloat16_as_ushort(h3) << 16) | __bfloat16_as_ushort(h2);
    ll.x = ((uint32_t)__bfloat16_as_ushort(l1) << 16) | __bfloat16_as_ushort(l0);
    ll.y = ((uint32_t)__bfloat16_as_ushort(l3) << 16) | __bfloat16_as_ushort(l2);
    size_t base = (size_t)row * KST_ + col;
    *reinterpret_cast<uint2*>(&g_a2[base])       = hh;
    *reinterpret_cast<uint2*>(&g_a2[base + 768]) = ll;
}

// ---------------- kernel 3: persistent pipelined bf16 mma.sync GEMM ----------------
// Logical C[M, ldc] = sum over 36 chunks: A-chunk x B-chunk (split-bf16 3-term schedule)
//   chunk kc: A offset = (kc<24 ? kc : kc-24)*64 ; B offset = (kc<12 ? kc : kc-12)*64
__global__ __launch_bounds__(256, 2) void gemm_kernel(
    const __nv_bfloat16* __restrict__ A, const __nv_bfloat16* __restrict__ B,
    const float* __restrict__ bias, float* __restrict__ C, int ldc,
    int ntn, int ntiles) {
    extern __shared__ char smem[];
    const uint32_t sb = smem_u32(smem);
    const int tid = threadIdx.x, lane = tid & 31, wid = tid >> 5;
    const int wm = (wid >> 2) * 64;     // 2 m-warps x 64
    const int wn = (wid & 3) * 32;      // 4 n-warps x 32

    const int arow = tid >> 3, acg = tid & 7;

    // ldmatrix lane constants
    const int a_row_l = wm + (lane & 15);
    const uint32_t a_xor = (uint32_t)(a_row_l & 7) << 4;
    const uint32_t a_k2 = (uint32_t)(lane >> 4) * 16;
    const int gq = lane >> 3;
    const int b_row_l = wn + (gq >> 1) * 8 + (lane & 7);
    const uint32_t b_xor = (uint32_t)(b_row_l & 7) << 4;
    const uint32_t b_k2 = (uint32_t)(gq & 1) * 16;

#define LOAD_A_(st_, base_, kc_)                                                    \
    {                                                                               \
        int k0_ = (((kc_) < 24) ? (kc_) : (kc_) - 24) * BK_;                        \
        _Pragma("unroll")                                                           \
        for (int it_ = 0; it_ < 4; it_++) {                                         \
            int row_ = arow + it_ * 32;                                             \
            uint32_t so_ = (st_) + (uint32_t)row_ * 128 +                           \
                           (((uint32_t)acg * 16) ^ ((uint32_t)(row_ & 7) << 4));    \
            cp_async16(so_, (base_) + (size_t)row_ * KST_ + k0_ + acg * 8);         \
        }                                                                           \
    }
#define LOAD_B_(st_, base_, kc_)                                                    \
    {                                                                               \
        int k0_ = (((kc_) < 12) ? (kc_) : (kc_) - 12) * BK_;                        \
        _Pragma("unroll")                                                           \
        for (int it_ = 0; it_ < 4; it_++) {                                         \
            int row_ = arow + it_ * 32;                                             \
            uint32_t so_ = (st_) + OFF_B_ + (uint32_t)row_ * 128 +                  \
                           (((uint32_t)acg * 16) ^ ((uint32_t)(row_ & 7) << 4));    \
            cp_async16(so_, (base_) + (size_t)row_ * KST_ + k0_ + acg * 8);         \
        }                                                                           \
    }
#define LOAD_FRAGS_(st, ks, buf)                                                    \
    {                                                                               \
        _Pragma("unroll")                                                           \
        for (int mf_ = 0; mf_ < 4; mf_++) {                                         \
            uint32_t ad_ = (st) + (uint32_t)(a_row_l + mf_ * 16) * 128 +            \
                           (((uint32_t)((ks) * 32) + a_k2) ^ a_xor);                \
            ldsm_x4(Af[buf][mf_][0], Af[buf][mf_][1], Af[buf][mf_][2],              \
                    Af[buf][mf_][3], ad_);                                          \
        }                                                                           \
        _Pragma("unroll")                                                           \
        for (int np_ = 0; np_ < 2; np_++) {                                         \
            uint32_t bd_ = (st) + OFF_B_ + (uint32_t)(b_row_l + np_ * 16) * 128 +   \
                           (((uint32_t)((ks) * 32) + b_k2) ^ b_xor);                \
            uint32_t r0_, r1_, r2_, r3_;                                            \
            ldsm_x4(r0_, r1_, r2_, r3_, bd_);                                       \
            Bf[buf][np_ * 2][0] = r0_; Bf[buf][np_ * 2][1] = r1_;                   \
            Bf[buf][np_ * 2 + 1][0] = r2_; Bf[buf][np_ * 2 + 1][1] = r3_;           \
        }                                                                           \
    }

    // ---- load-stream state (runs 2 chunks ahead, across tile boundaries) ----
    int ldTile = blockIdx.x;
    int ldKc = 0;
    const __nv_bfloat16* ldA = A + (size_t)(ldTile / ntn) * BM_ * KST_;
    const __nv_bfloat16* ldB = B + (size_t)(ldTile % ntn) * BN_ * KST_;

    uint32_t Af[2][4][4], Bf[2][4][2];
    float acc[4][4][4];

    // prologue: chunks 0 and 1 of first tile (KITERS_ > 2 always)
    LOAD_A_(sb, ldA, 0); LOAD_B_(sb, ldB, 0); CP_COMMIT_();
    LOAD_A_(sb + STAGE_BYTES_, ldA, 1); LOAD_B_(sb + STAGE_BYTES_, ldB, 1); CP_COMMIT_();
    ldKc = 2;

    CP_WAIT_(1);
    __syncthreads();
    LOAD_FRAGS_(sb, 0, 0);

    const uint32_t stage_off[3] = {0u, STAGE_BYTES_, 2u * STAGE_BYTES_};
    int cur = 0;

    for (int tile = blockIdx.x; tile < ntiles; tile += gridDim.x) {
#pragma unroll
        for (int i = 0; i < 4; i++)
#pragma unroll
            for (int j = 0; j < 4; j++)
#pragma unroll
                for (int r = 0; r < 4; r++) acc[i][j][r] = 0.f;

        for (int kc = 0; kc < KITERS_; kc++) {
            const uint32_t st = sb + stage_off[cur];
            int ldstage = cur + 2; if (ldstage >= 3) ldstage -= 3;
            const uint32_t lst = sb + stage_off[ldstage];
            int nxt = cur + 1; if (nxt >= 3) nxt -= 3;
            const bool doload = ldTile < ntiles;
#pragma unroll
            for (int ks = 0; ks < 4; ks++) {
                if (ks == 0 && doload) { LOAD_A_(lst, ldA, ldKc); }
                if (ks == 1) {
                    if (doload) { LOAD_B_(lst, ldB, ldKc); }
                    CP_COMMIT_();
                    // advance load stream
                    if (++ldKc == KITERS_) {
                        ldKc = 0;
                        ldTile += gridDim.x;
                        if (ldTile < ntiles) {
                            ldA = A + (size_t)(ldTile / ntn) * BM_ * KST_;
                            ldB = B + (size_t)(ldTile % ntn) * BN_ * KST_;
                        }
                    }
                }
                if (ks == 3) {
                    const bool more = (kc + 1 < KITERS_) || (tile + gridDim.x < ntiles);
                    if (more) {
                        CP_WAIT_(1);
                        __syncthreads();
                        LOAD_FRAGS_(sb + stage_off[nxt], 0, 0);
                    }
                } else {
                    LOAD_FRAGS_(st, ks + 1, (ks + 1) & 1);
                }
#pragma unroll
                for (int mf = 0; mf < 4; mf++)
#pragma unroll
                    for (int nf = 0; nf < 4; nf++)
                        mma_bf16(acc[mf][nf], Af[ks & 1][mf], Bf[ks & 1][nf]);
            }
            cur = nxt;
        }

        // epilogue for this tile: fp32 stores + bias (no smem use -> no sync needed)
        const int tm = tile / ntn, tn = tile - tm * ntn;
        const int crow0 = tm * BM_ + wm + (lane >> 2);
        const int ccol0 = tn * BN_ + wn + (lane & 3) * 2;
#pragma unroll
        for (int mf = 0; mf < 4; mf++) {
#pragma unroll
            for (int nf = 0; nf < 4; nf++) {
                int col = ccol0 + nf * 8;
                float b0 = bias[col], b1 = bias[col + 1];
                int r0 = crow0 + mf * 16;
                float2 v0 = make_float2(acc[mf][nf][0] + b0, acc[mf][nf][1] + b1);
                float2 v1 = make_float2(acc[mf][nf][2] + b0, acc[mf][nf][3] + b1);
                *reinterpret_cast<float2*>(C + (size_t)r0 * ldc + col) = v0;
                *reinterpret_cast<float2*>(C + (size_t)(r0 + 8) * ldc + col) = v1;
            }
        }
    }
#undef LOAD_A_
#undef LOAD_B_
#undef LOAD_FRAGS_
}

// ---------------- kernel 4: 3-tap local attention (warp per token x head-pair) ----------------
__global__ __launch_bounds__(256) void local_attn_kernel() {
    int gw = (blockIdx.x * 256 + threadIdx.x) >> 5;      // KBT_*6 warps
    int lid = threadIdx.x & 31;
    int token = gw / 6;
    int hp = gw - token * 6;
    int t = token & (KT_ - 1);
    size_t base = (size_t)token * KNQKV_ + hp * 128 + lid * 4;  // q at +0, k +768, v +1536

    float4 q = *reinterpret_cast<const float4*>(&g_qkv[base]);

    float sc[3];
#pragma unroll
    for (int j = 0; j < 3; j++) {
        int off = (j - 1) * KINT_;
        bool valid = ((unsigned)(t + off) < (unsigned)KT_);
        float p = 0.f;
        if (valid) {
            const float4 k = *reinterpret_cast<const float4*>(
                &g_qkv[base + (long long)off * KNQKV_ + 768]);
            p = q.x * k.x + q.y * k.y + q.z * k.z + q.w * k.w;
        }
#pragma unroll
        for (int m = 8; m; m >>= 1) p += __shfl_xor_sync(0xffffffffu, p, m);
        sc[j] = valid ? p * 0.125f : -INFINITY;          // 1/sqrt(64)
    }
    float mx = fmaxf(sc[0], fmaxf(sc[1], sc[2]));
    float e[3], den = 0.f;
#pragma unroll
    for (int j = 0; j < 3; j++) { e[j] = __expf(sc[j] - mx); den += e[j]; }
    float rden = 1.f / den;

    float a0 = 0.f, a1 = 0.f, a2 = 0.f, a3 = 0.f;
#pragma unroll
    for (int j = 0; j < 3; j++) {
        int off = (j - 1) * KINT_;
        if ((unsigned)(t + off) < (unsigned)KT_) {
            const float4 v = *reinterpret_cast<const float4*>(
                &g_qkv[base + (long long)off * KNQKV_ + 1536]);
            float w = e[j] * rden;
            a0 += w * v.x; a1 += w * v.y; a2 += w * v.z; a3 += w * v.w;
        }
    }
    __nv_bfloat16 h0 = __float2bfloat16(a0), h1 = __float2bfloat16(a1);
    __nv_bfloat16 h2 = __float2bfloat16(a2), h3 = __float2bfloat16(a3);
    __nv_bfloat16 l0 = __float2bfloat16(a0 - __bfloat162float(h0));
    __nv_bfloat16 l1 = __float2bfloat16(a1 - __bfloat162float(h1));
    __nv_bfloat16 l2 = __float2bfloat16(a2 - __bfloat162float(h2));
    __nv_bfloat16 l3 = __float2bfloat16(a3 - __bfloat162float(h3));
    uint2 hh, ll;
    hh.x = ((uint32_t)__bfloat16_as_ushort(h1) << 16) | __bfloat16_as_ushort(h0);
    hh.y = ((uint32_t)__bfloat16_as_ushort(h3) << 16) | __bfloat16_as_ushort(h2);
    ll.x = ((uint32_t)__bfloat16_as_ushort(l1) << 16) | __bfloat16_as_ushort(l0);
    ll.y = ((uint32_t)__bfloat16_as_ushort(l3) << 16) | __bfloat16_as_ushort(l2);
    size_t base2 = (size_t)token * KST_ + hp * 128 + lid * 4;
    *reinterpret_cast<uint2*>(&g_a2[base2])       = hh;
    *reinterpret_cast<uint2*>(&g_a2[base2 + 768]) = ll;
}

// ---------------- kernel 5: residual + LayerNorm ----------------
__global__ __launch_bounds__(256) void ln_kernel(
    const float* __restrict__ x, const float* __restrict__ gamma,
    const float* __restrict__ beta, float* __restrict__ out) {
    __shared__ float s_sum[8], s_sq[8];
    int r = blockIdx.x, tid = threadIdx.x, wid = tid >> 5, lid = tid & 31;
    size_t base = (size_t)r * KD_;

    float y[3], s = 0.f, s2 = 0.f;
#pragma unroll
    for (int i = 0; i < 3; i++) {
        int c = tid + i * 256;
        float v = g_o[base + c] + x[base + c];
        y[i] = v; s += v; s2 += v * v;
    }
#pragma unroll
    for (int m = 16; m; m >>= 1) {
        s  += __shfl_xor_sync(0xffffffffu, s, m);
        s2 += __shfl_xor_sync(0xffffffffu, s2, m);
    }
    if (lid == 0) { s_sum[wid] = s; s_sq[wid] = s2; }
    __syncthreads();
    float ts = 0.f, ts2 = 0.f;
#pragma unroll
    for (int i = 0; i < 8; i++) { ts += s_sum[i]; ts2 += s_sq[i]; }
    float mean = ts * (1.f / KD_);
    float var  = ts2 * (1.f / KD_) - mean * mean;
    float inv  = rsqrtf(var + 1e-5f);
#pragma unroll
    for (int i = 0; i < 3; i++) {
        int c = tid + i * 256;
        out[base + c] = (y[i] - mean) * inv * gamma[c] + beta[c];
    }
}

// ---------------- launch ----------------
extern "C" void kernel_launch(void* const* d_in, const int* in_sizes, int n_in,
                              void* d_out, int out_size) {
    const float* x     = (const float*)d_in[0];
    const float* Wq    = (const float*)d_in[1];
    const float* bq    = (const float*)d_in[2];
    const float* Wk    = (const float*)d_in[3];
    const float* bk    = (const float*)d_in[4];
    const float* Wv    = (const float*)d_in[5];
    const float* bv    = (const float*)d_in[6];
    const float* Wo    = (const float*)d_in[7];
    const float* bo    = (const float*)d_in[8];
    const float* gamma = (const float*)d_in[9];
    const float* beta  = (const float*)d_in[10];

    void *p_a2, *p_w2, *p_qkv, *p_o, *p_bqkv;
    cudaGetSymbolAddress(&p_a2,  g_a2);
    cudaGetSymbolAddress(&p_w2,  g_w2);
    cudaGetSymbolAddress(&p_qkv, g_qkv);
    cudaGetSymbolAddress(&p_o,   g_o);
    cudaGetSymbolAddress(&p_bqkv, g_bqkv);

    const __nv_bfloat16* a2 = (const __nv_bfloat16*)p_a2;
    const __nv_bfloat16* w2 = (const __nv_bfloat16*)p_w2;
    const size_t WSTRIDE = (size_t)KD_ * KST_;

    cudaFuncSetAttribute(gemm_kernel,
                         cudaFuncAttributeMaxDynamicSharedMemorySize, (int)SMEM_BYTES_);

    prep_weights_kernel<<<WELEM_ / 256, 256>>>(Wq, Wk, Wv, Wo, bq, bk, bv);
    split_x_kernel<<<(int)(KNELEM_ / 4 / 256), 256>>>(x);

    // fused QKV: C[32768, 2304], tiles = 18 x 256 = 4608
    {
        int ntn = KNQKV_ / BN_, ntiles = ntn * (KBT_ / BM_);
        int grid = ntiles < NPERSIST_ ? ntiles : NPERSIST_;
        gemm_kernel<<<grid, 256, SMEM_BYTES_>>>(a2, w2, (const float*)p_bqkv,
                                                (float*)p_qkv, KNQKV_, ntn, ntiles);
    }
    // attention: 32768 tokens * 6 head-pairs = 196608 warps = 24576 blocks
    local_attn_kernel<<<KBT_ * 6 / 8, 256>>>();
    // O projection: C[32768, 768], tiles = 6 x 256 = 1536
    {
        int ntn = KD_ / BN_, ntiles = ntn * (KBT_ / BM_);
        int grid = ntiles < NPERSIST_ ? ntiles : NPERSIST_;
        gemm_kernel<<<grid, 256, SMEM_BYTES_>>>(a2, w2 + 3 * WSTRIDE, bo,
                                                (float*)p_o, KD_, ntn, ntiles);
    }
    ln_kernel<<<KBT_, 256>>>(x, gamma, beta, (float*)d_out);
}

// round 11
// speedup vs baseline: 1.0720x; 1.0720x over previous
#include <cuda_runtime.h>
#include <cuda_bf16.h>
#include <cstdint>
#include <math.h>

// ---------------- problem constants ----------------
#define KB_   8
#define KT_   4096
#define KD_   768
#define KH_   12
#define KHD_  64
#define KINT_ 3
#define KBT_  (KB_ * KT_)                 // 32768
#define KNELEM_ ((size_t)KBT_ * KD_)      // 25165824
#define KST_  1536                        // stored K width: [hi(768) | lo(768)]
#define KNQKV_ 2304                       // Wq|Wk|Wv stacked along N
#define WELEM_ (KD_ * KD_)

// GEMM tiling: 128x128 CTA, 64x32 warp, 3 stages -> 2 CTAs/SM
#define BM_ 128
#define BN_ 128
#define BK_ 64
#define KITERS_ 36                        // hh(12) + hl(12) + lh(12) chunk schedule
#define STAGES_ 3
#define STAGE_BYTES_ 32768u               // A 16KB + B 16KB
#define OFF_B_ 16384u
#define SMEM_BYTES_ (STAGES_ * STAGE_BYTES_)   // 98304

// ---------------- device scratch ----------------
__device__ __nv_bfloat16 g_a2[(size_t)KBT_ * KST_];          // split activations [hi|lo]
__device__ __nv_bfloat16 g_w2[4 * (size_t)KD_ * KST_];       // split weights [Wh|Wl] per matrix
__device__ float g_bqkv[KNQKV_];                             // concat bias q|k|v
__device__ float g_qkv[(size_t)KBT_ * KNQKV_];               // fused QKV output
__device__ float g_o[KNELEM_];

// ---------------- helpers ----------------
__device__ __forceinline__ uint32_t smem_u32(const void* p) {
    return (uint32_t)__cvta_generic_to_shared(p);
}

__device__ __forceinline__ void cp_async16(uint32_t saddr, const void* gaddr) {
    asm volatile("cp.async.cg.shared.global [%0], [%1], 16;" :: "r"(saddr), "l"(gaddr));
}
#define CP_COMMIT_()  asm volatile("cp.async.commit_group;" ::: "memory")
#define CP_WAIT_(n)   asm volatile("cp.async.wait_group %0;" :: "n"(n) : "memory")

__device__ __forceinline__ void ldsm_x4(uint32_t& r0, uint32_t& r1, uint32_t& r2, uint32_t& r3,
                                        uint32_t addr) {
    asm volatile("ldmatrix.sync.aligned.m8n8.x4.shared.b16 {%0,%1,%2,%3}, [%4];"
                 : "=r"(r0), "=r"(r1), "=r"(r2), "=r"(r3) : "r"(addr));
}

__device__ __forceinline__ void mma_bf16(float* c, const uint32_t* a, const uint32_t* b) {
    asm volatile(
        "mma.sync.aligned.m16n8k16.row.col.f32.bf16.bf16.f32 "
        "{%0,%1,%2,%3}, {%4,%5,%6,%7}, {%8,%9}, {%0,%1,%2,%3};"
        : "+f"(c[0]), "+f"(c[1]), "+f"(c[2]), "+f"(c[3])
        : "r"(a[0]), "r"(a[1]), "r"(a[2]), "r"(a[3]), "r"(b[0]), "r"(b[1]));
}

// ---------------- kernel 1: transpose + split weights, concat bias ----------------
__global__ __launch_bounds__(256) void prep_weights_kernel(
    const float* __restrict__ Wq, const float* __restrict__ Wk,
    const float* __restrict__ Wv, const float* __restrict__ Wo,
    const float* __restrict__ bq, const float* __restrict__ bk,
    const float* __restrict__ bv) {
    int idx = blockIdx.x * 256 + threadIdx.x;       // over D*D
    int n = idx / KD_;
    int k = idx - n * KD_;
    const float* Ws[4] = {Wq, Wk, Wv, Wo};
#pragma unroll
    for (int w = 0; w < 4; w++) {
        float val = Ws[w][(size_t)k * KD_ + n];     // W[k][n] -> B[n][k]
        __nv_bfloat16 hi = __float2bfloat16(val);
        __nv_bfloat16 lo = __float2bfloat16(val - __bfloat162float(hi));
        size_t base = (size_t)w * KD_ * KST_ + (size_t)n * KST_;
        g_w2[base + k]       = hi;
        g_w2[base + 768 + k] = lo;
    }
    if (idx < KNQKV_) {
        g_bqkv[idx] = (idx < 768) ? bq[idx] : (idx < 1536) ? bk[idx - 768] : bv[idx - 1536];
    }
}

// ---------------- kernel 2: split x -> [hi | lo] rows of 1536 (float4) ----------------
__global__ __launch_bounds__(256) void split_x_kernel(const float* __restrict__ x) {
    long long gid = (long long)blockIdx.x * 256 + threadIdx.x;   // over KNELEM/4
    long long i = gid * 4;
    int row = (int)(i / KD_);
    int col = (int)(i - (long long)row * KD_);
    float4 v = *reinterpret_cast<const float4*>(x + i);
    __nv_bfloat16 h0 = __float2bfloat16(v.x), h1 = __float2bfloat16(v.y);
    __nv_bfloat16 h2 = __float2bfloat16(v.z), h3 = __float2bfloat16(v.w);
    __nv_bfloat16 l0 = __float2bfloat16(v.x - __bfloat162float(h0));
    __nv_bfloat16 l1 = __float2bfloat16(v.y - __bfloat162float(h1));
    __nv_bfloat16 l2 = __float2bfloat16(v.z - __bfloat162float(h2));
    __nv_bfloat16 l3 = __float2bfloat16(v.w - __bfloat162float(h3));
    uint2 hh, ll;
    hh.x = ((uint32_t)__bfloat16_as_ushort(h1) << 16) | __bfloat16_as_ushort(h0);
    hh.y = ((uint32_t)__bfloat16_as_ushort(h3) << 16) | __bfloat16_as_ushort(h2);
    ll.x = ((uint32_t)__bfloat16_as_ushort(l1) << 16) | __bfloat16_as_ushort(l0);
    ll.y = ((uint32_t)__bfloat16_as_ushort(l3) << 16) | __bfloat16_as_ushort(l2);
    size_t base = (size_t)row * KST_ + col;
    *reinterpret_cast<uint2*>(&g_a2[base])       = hh;
    *reinterpret_cast<uint2*>(&g_a2[base + 768]) = ll;
}

// ---------------- kernel 3: pipelined bf16 mma.sync GEMM (128x128 CTA, 64x32 warp, 2 CTA/SM) ----------------
// C = sum over 36 chunks: A-chunk x B-chunk (split-bf16 3-term schedule)
//   chunk kc: A offset = (kc<24 ? kc : kc-24)*64 ; B offset = (kc<12 ? kc : kc-12)*64
//   -> kc 0-11: Ah*Bh ; kc 12-23: Ah*Bl ; kc 24-35: Al*Bh
__global__ __launch_bounds__(256, 2) void gemm_kernel(
    const __nv_bfloat16* __restrict__ A, const __nv_bfloat16* __restrict__ B,
    const float* __restrict__ bias, float* __restrict__ C, int ldc) {
    extern __shared__ char smem[];
    const uint32_t sb = smem_u32(smem);
    const int tid = threadIdx.x, lane = tid & 31, wid = tid >> 5;
    const int m0 = blockIdx.y * BM_;
    const int n0 = blockIdx.x * BN_;
    const int wm = (wid >> 2) * 64;     // 2 m-warps x 64
    const int wn = (wid & 3) * 32;      // 4 n-warps x 32

    const int arow = tid >> 3, acg = tid & 7;
    const __nv_bfloat16* Abase = A + (size_t)m0 * KST_;
    const __nv_bfloat16* Bbase = B + (size_t)n0 * KST_;

    // ldmatrix lane constants
    const int a_row_l = wm + (lane & 15);
    const uint32_t a_xor = (uint32_t)(a_row_l & 7) << 4;
    const uint32_t a_k2 = (uint32_t)(lane >> 4) * 16;
    const int gq = lane >> 3;
    const int b_row_l = wn + (gq >> 1) * 8 + (lane & 7);
    const uint32_t b_xor = (uint32_t)(b_row_l & 7) << 4;
    const uint32_t b_k2 = (uint32_t)(gq & 1) * 16;

    float acc[4][4][4];
#pragma unroll
    for (int i = 0; i < 4; i++)
#pragma unroll
        for (int j = 0; j < 4; j++)
#pragma unroll
            for (int r = 0; r < 4; r++) acc[i][j][r] = 0.f;

#define LOAD_A_(st_, kc_)                                                           \
    {                                                                               \
        int k0_ = (((kc_) < 24) ? (kc_) : (kc_) - 24) * BK_;                        \
        _Pragma("unroll")                                                           \
        for (int it_ = 0; it_ < 4; it_++) {                                         \
            int row_ = arow + it_ * 32;                                             \
            uint32_t so_ = (st_) + (uint32_t)row_ * 128 +                           \
                           (((uint32_t)acg * 16) ^ ((uint32_t)(row_ & 7) << 4));    \
            cp_async16(so_, Abase + (size_t)row_ * KST_ + k0_ + acg * 8);           \
        }                                                                           \
    }
#define LOAD_B_(st_, kc_)                                                           \
    {                                                                               \
        int k0_ = (((kc_) < 12) ? (kc_) : (kc_) - 12) * BK_;                        \
        _Pragma("unroll")                                                           \
        for (int it_ = 0; it_ < 4; it_++) {                                         \
            int row_ = arow + it_ * 32;                                             \
            uint32_t so_ = (st_) + OFF_B_ + (uint32_t)row_ * 128 +                  \
                           (((uint32_t)acg * 16) ^ ((uint32_t)(row_ & 7) << 4));    \
            cp_async16(so_, Bbase + (size_t)row_ * KST_ + k0_ + acg * 8);           \
        }                                                                           \
    }

    // prologue: stages 0..1
    LOAD_A_(sb, 0); LOAD_B_(sb, 0); CP_COMMIT_();
    LOAD_A_(sb + STAGE_BYTES_, 1); LOAD_B_(sb + STAGE_BYTES_, 1); CP_COMMIT_();

    uint32_t Af[2][4][4], Bf[2][4][2];

#define LOAD_FRAGS_(st, ks, buf)                                                    \
    {                                                                               \
        _Pragma("unroll")                                                           \
        for (int mf_ = 0; mf_ < 4; mf_++) {                                         \
            uint32_t ad_ = (st) + (uint32_t)(a_row_l + mf_ * 16) * 128 +            \
                           (((uint32_t)((ks) * 32) + a_k2) ^ a_xor);                \
            ldsm_x4(Af[buf][mf_][0], Af[buf][mf_][1], Af[buf][mf_][2],              \
                    Af[buf][mf_][3], ad_);                                          \
        }                                                                           \
        _Pragma("unroll")                                                           \
        for (int np_ = 0; np_ < 2; np_++) {                                         \
            uint32_t bd_ = (st) + OFF_B_ + (uint32_t)(b_row_l + np_ * 16) * 128 +   \
                           (((uint32_t)((ks) * 32) + b_k2) ^ b_xor);                \
            uint32_t r0_, r1_, r2_, r3_;                                            \
            ldsm_x4(r0_, r1_, r2_, r3_, bd_);                                       \
            Bf[buf][np_ * 2][0] = r0_; Bf[buf][np_ * 2][1] = r1_;                   \
            Bf[buf][np_ * 2 + 1][0] = r2_; Bf[buf][np_ * 2 + 1][1] = r3_;           \
        }                                                                           \
    }

    // wait stage 0, preload its ks0 fragments
    CP_WAIT_(1);
    __syncthreads();
    LOAD_FRAGS_(sb, 0, 0);

    const uint32_t stage_off[3] = {0u, STAGE_BYTES_, 2u * STAGE_BYTES_};
    int cur = 0;                 // stage index of kc
    for (int kc = 0; kc < KITERS_; kc++) {
        const uint32_t st = sb + stage_off[cur];
        int ldstage = cur + 2; if (ldstage >= 3) ldstage -= 3;
        const uint32_t lst = sb + stage_off[ldstage];
        int nxt = cur + 1; if (nxt >= 3) nxt -= 3;
        const int ld = kc + 2;
        const bool doload = ld < KITERS_;
#pragma unroll
        for (int ks = 0; ks < 4; ks++) {
            if (ks == 0 && doload) { LOAD_A_(lst, ld); }
            if (ks == 1 && doload) { LOAD_B_(lst, ld); }
            if (ks == 1) { CP_COMMIT_(); }
            if (ks == 3) {
                if (kc + 1 < KITERS_) {
                    CP_WAIT_(1);
                    __syncthreads();
                    LOAD_FRAGS_(sb + stage_off[nxt], 0, 0);
                }
            } else {
                LOAD_FRAGS_(st, ks + 1, (ks + 1) & 1);
            }
#pragma unroll
            for (int mf = 0; mf < 4; mf++)
#pragma unroll
                for (int nf = 0; nf < 4; nf++)
                    mma_bf16(acc[mf][nf], Af[ks & 1][mf], Bf[ks & 1][nf]);
        }
        cur = nxt;
    }

    // epilogue: fp32 stores + bias
    const int crow0 = m0 + wm + (lane >> 2);
    const int ccol0 = n0 + wn + (lane & 3) * 2;
#pragma unroll
    for (int mf = 0; mf < 4; mf++) {
#pragma unroll
        for (int nf = 0; nf < 4; nf++) {
            int col = ccol0 + nf * 8;
            float b0 = bias[col], b1 = bias[col + 1];
            int r0 = crow0 + mf * 16;
            float2 v0 = make_float2(acc[mf][nf][0] + b0, acc[mf][nf][1] + b1);
            float2 v1 = make_float2(acc[mf][nf][2] + b0, acc[mf][nf][3] + b1);
            *reinterpret_cast<float2*>(C + (size_t)r0 * ldc + col) = v0;
            *reinterpret_cast<float2*>(C + (size_t)(r0 + 8) * ldc + col) = v1;
        }
    }
#undef LOAD_A_
#undef LOAD_B_
#undef LOAD_FRAGS_
}

// ---------------- kernel 4: 3-tap local attention (warp per token x head-pair) ----------------
__global__ __launch_bounds__(256) void local_attn_kernel() {
    int gw = (blockIdx.x * 256 + threadIdx.x) >> 5;      // KBT_*6 warps
    int lid = threadIdx.x & 31;
    int token = gw / 6;
    int hp = gw - token * 6;
    int t = token & (KT_ - 1);
    size_t base = (size_t)token * KNQKV_ + hp * 128 + lid * 4;  // q at +0, k +768, v +1536

    float4 q = *reinterpret_cast<const float4*>(&g_qkv[base]);

    float sc[3];
#pragma unroll
    for (int j = 0; j < 3; j++) {
        int off = (j - 1) * KINT_;
        bool valid = ((unsigned)(t + off) < (unsigned)KT_);
        float p = 0.f;
        if (valid) {
            const float4 k = *reinterpret_cast<const float4*>(
                &g_qkv[base + (long long)off * KNQKV_ + 768]);
            p = q.x * k.x + q.y * k.y + q.z * k.z + q.w * k.w;
        }
#pragma unroll
        for (int m = 8; m; m >>= 1) p += __shfl_xor_sync(0xffffffffu, p, m);
        sc[j] = valid ? p * 0.125f : -INFINITY;          // 1/sqrt(64)
    }
    float mx = fmaxf(sc[0], fmaxf(sc[1], sc[2]));
    float e[3], den = 0.f;
#pragma unroll
    for (int j = 0; j < 3; j++) { e[j] = __expf(sc[j] - mx); den += e[j]; }
    float rden = 1.f / den;

    float a0 = 0.f, a1 = 0.f, a2 = 0.f, a3 = 0.f;
#pragma unroll
    for (int j = 0; j < 3; j++) {
        int off = (j - 1) * KINT_;
        if ((unsigned)(t + off) < (unsigned)KT_) {
            const float4 v = *reinterpret_cast<const float4*>(
                &g_qkv[base + (long long)off * KNQKV_ + 1536]);
            float w = e[j] * rden;
            a0 += w * v.x; a1 += w * v.y; a2 += w * v.z; a3 += w * v.w;
        }
    }
    __nv_bfloat16 h0 = __float2bfloat16(a0), h1 = __float2bfloat16(a1);
    __nv_bfloat16 h2 = __float2bfloat16(a2), h3 = __float2bfloat16(a3);
    __nv_bfloat16 l0 = __float2bfloat16(a0 - __bfloat162float(h0));
    __nv_bfloat16 l1 = __float2bfloat16(a1 - __bfloat162float(h1));
    __nv_bfloat16 l2 = __float2bfloat16(a2 - __bfloat162float(h2));
    __nv_bfloat16 l3 = __float2bfloat16(a3 - __bfloat162float(h3));
    uint2 hh, ll;
    hh.x = ((uint32_t)__bfloat16_as_ushort(h1) << 16) | __bfloat16_as_ushort(h0);
    hh.y = ((uint32_t)__bfloat16_as_ushort(h3) << 16) | __bfloat16_as_ushort(h2);
    ll.x = ((uint32_t)__bfloat16_as_ushort(l1) << 16) | __bfloat16_as_ushort(l0);
    ll.y = ((uint32_t)__bfloat16_as_ushort(l3) << 16) | __bfloat16_as_ushort(l2);
    size_t base2 = (size_t)token * KST_ + hp * 128 + lid * 4;
    *reinterpret_cast<uint2*>(&g_a2[base2])       = hh;
    *reinterpret_cast<uint2*>(&g_a2[base2 + 768]) = ll;
}

// ---------------- kernel 5: residual + LayerNorm ----------------
__global__ __launch_bounds__(256) void ln_kernel(
    const float* __restrict__ x, const float* __restrict__ gamma,
    const float* __restrict__ beta, float* __restrict__ out) {
    __shared__ float s_sum[8], s_sq[8];
    int r = blockIdx.x, tid = threadIdx.x, wid = tid >> 5, lid = tid & 31;
    size_t base = (size_t)r * KD_;

    float y[3], s = 0.f, s2 = 0.f;
#pragma unroll
    for (int i = 0; i < 3; i++) {
        int c = tid + i * 256;
        float v = g_o[base + c] + x[base + c];
        y[i] = v; s += v; s2 += v * v;
    }
#pragma unroll
    for (int m = 16; m; m >>= 1) {
        s  += __shfl_xor_sync(0xffffffffu, s, m);
        s2 += __shfl_xor_sync(0xffffffffu, s2, m);
    }
    if (lid == 0) { s_sum[wid] = s; s_sq[wid] = s2; }
    __syncthreads();
    float ts = 0.f, ts2 = 0.f;
#pragma unroll
    for (int i = 0; i < 8; i++) { ts += s_sum[i]; ts2 += s_sq[i]; }
    float mean = ts * (1.f / KD_);
    float var  = ts2 * (1.f / KD_) - mean * mean;
    float inv  = rsqrtf(var + 1e-5f);
#pragma unroll
    for (int i = 0; i < 3; i++) {
        int c = tid + i * 256;
        out[base + c] = (y[i] - mean) * inv * gamma[c] + beta[c];
    }
}

// ---------------- launch ----------------
extern "C" void kernel_launch(void* const* d_in, const int* in_sizes, int n_in,
                              void* d_out, int out_size) {
    const float* x     = (const float*)d_in[0];
    const float* Wq    = (const float*)d_in[1];
    const float* bq    = (const float*)d_in[2];
    const float* Wk    = (const float*)d_in[3];
    const float* bk    = (const float*)d_in[4];
    const float* Wv    = (const float*)d_in[5];
    const float* bv    = (const float*)d_in[6];
    const float* Wo    = (const float*)d_in[7];
    const float* bo    = (const float*)d_in[8];
    const float* gamma = (const float*)d_in[9];
    const float* beta  = (const float*)d_in[10];

    void *p_a2, *p_w2, *p_qkv, *p_o, *p_bqkv;
    cudaGetSymbolAddress(&p_a2,  g_a2);
    cudaGetSymbolAddress(&p_w2,  g_w2);
    cudaGetSymbolAddress(&p_qkv, g_qkv);
    cudaGetSymbolAddress(&p_o,   g_o);
    cudaGetSymbolAddress(&p_bqkv, g_bqkv);

    const __nv_bfloat16* a2 = (const __nv_bfloat16*)p_a2;
    const __nv_bfloat16* w2 = (const __nv_bfloat16*)p_w2;
    const size_t WSTRIDE = (size_t)KD_ * KST_;

    cudaFuncSetAttribute(gemm_kernel,
                         cudaFuncAttributeMaxDynamicSharedMemorySize, (int)SMEM_BYTES_);

    prep_weights_kernel<<<WELEM_ / 256, 256>>>(Wq, Wk, Wv, Wo, bq, bk, bv);
    split_x_kernel<<<(int)(KNELEM_ / 4 / 256), 256>>>(x);

    // fused QKV: C[32768, 2304]
    dim3 gqkv(KNQKV_ / BN_, KBT_ / BM_);   // (18, 256)
    gemm_kernel<<<gqkv, 256, SMEM_BYTES_>>>(a2, w2, (const float*)p_bqkv,
                                            (float*)p_qkv, KNQKV_);
    // attention: 32768 tokens * 6 head-pairs = 196608 warps = 24576 blocks
    local_attn_kernel<<<KBT_ * 6 / 8, 256>>>();
    // O projection: C[32768, 768]
    dim3 go(KD_ / BN_, KBT_ / BM_);        // (6, 256)
    gemm_kernel<<<go, 256, SMEM_BYTES_>>>(a2, w2 + 3 * WSTRIDE, bo, (float*)p_o, KD_);
    ln_kernel<<<KBT_, 256>>>(x, gamma, beta, (float*)d_out);
}

// round 13
// speedup vs baseline: 1.3104x; 1.2224x over previous
#include <cuda_runtime.h>
#include <cuda_fp16.h>
#include <cstdint>
#include <math.h>

// ---------------- problem constants ----------------
#define KB_   8
#define KT_   4096
#define KD_   768
#define KH_   12
#define KHD_  64
#define KINT_ 3
#define KBT_  (KB_ * KT_)                 // 32768
#define KNELEM_ ((size_t)KBT_ * KD_)      // 25165824
#define KWST_ 1536                        // weight stored K width: [Wh(768) | Wl(768)]
#define KNQKV_ 2304                       // Wq|Wk|Wv stacked along N
#define WELEM_ (KD_ * KD_)

// GEMM tiling: 128x128 CTA, 64x32 warp, 3 stages -> 2 CTAs/SM
#define BM_ 128
#define BN_ 128
#define BK_ 64
#define KITERS_ 24                        // hh(12) + hl(12) chunk schedule (fp16 2-term)
#define STAGES_ 3
#define STAGE_BYTES_ 32768u               // A 16KB + B 16KB
#define OFF_B_ 16384u
#define SMEM_BYTES_ (STAGES_ * STAGE_BYTES_)   // 98304

// ---------------- device scratch ----------------
__device__ __half g_ah[KNELEM_];                             // fp16 activations (x, then attn)
__device__ __half g_w2[4 * (size_t)KD_ * KWST_];             // fp16 split weights [Wh|Wl] per matrix
__device__ float g_bqkv[KNQKV_];                             // concat bias q|k|v
__device__ float g_qkv[(size_t)KBT_ * KNQKV_];               // fused QKV output
__device__ float g_o[KNELEM_];

// ---------------- helpers ----------------
__device__ __forceinline__ uint32_t smem_u32(const void* p) {
    return (uint32_t)__cvta_generic_to_shared(p);
}

__device__ __forceinline__ void cp_async16(uint32_t saddr, const void* gaddr) {
    asm volatile("cp.async.cg.shared.global [%0], [%1], 16;" :: "r"(saddr), "l"(gaddr));
}
#define CP_COMMIT_()  asm volatile("cp.async.commit_group;" ::: "memory")
#define CP_WAIT_(n)   asm volatile("cp.async.wait_group %0;" :: "n"(n) : "memory")

__device__ __forceinline__ void ldsm_x4(uint32_t& r0, uint32_t& r1, uint32_t& r2, uint32_t& r3,
                                        uint32_t addr) {
    asm volatile("ldmatrix.sync.aligned.m8n8.x4.shared.b16 {%0,%1,%2,%3}, [%4];"
                 : "=r"(r0), "=r"(r1), "=r"(r2), "=r"(r3) : "r"(addr));
}

__device__ __forceinline__ void mma_f16(float* c, const uint32_t* a, const uint32_t* b) {
    asm volatile(
        "mma.sync.aligned.m16n8k16.row.col.f32.f16.f16.f32 "
        "{%0,%1,%2,%3}, {%4,%5,%6,%7}, {%8,%9}, {%0,%1,%2,%3};"
        : "+f"(c[0]), "+f"(c[1]), "+f"(c[2]), "+f"(c[3])
        : "r"(a[0]), "r"(a[1]), "r"(a[2]), "r"(a[3]), "r"(b[0]), "r"(b[1]));
}

// ---------------- kernel 1: transpose + fp16-split weights, concat bias ----------------
__global__ __launch_bounds__(256) void prep_weights_kernel(
    const float* __restrict__ Wq, const float* __restrict__ Wk,
    const float* __restrict__ Wv, const float* __restrict__ Wo,
    const float* __restrict__ bq, const float* __restrict__ bk,
    const float* __restrict__ bv) {
    int idx = blockIdx.x * 256 + threadIdx.x;       // over D*D
    int n = idx / KD_;
    int k = idx - n * KD_;
    const float* Ws[4] = {Wq, Wk, Wv, Wo};
#pragma unroll
    for (int w = 0; w < 4; w++) {
        float val = Ws[w][(size_t)k * KD_ + n];     // W[k][n] -> B[n][k]
        __half hi = __float2half(val);
        __half lo = __float2half(val - __half2float(hi));
        size_t base = (size_t)w * KD_ * KWST_ + (size_t)n * KWST_;
        g_w2[base + k]       = hi;
        g_w2[base + 768 + k] = lo;
    }
    if (idx < KNQKV_) {
        g_bqkv[idx] = (idx < 768) ? bq[idx] : (idx < 1536) ? bk[idx - 768] : bv[idx - 1536];
    }
}

// ---------------- kernel 2: convert x -> fp16 (float4 -> 4 halves) ----------------
__global__ __launch_bounds__(256) void split_x_kernel(const float* __restrict__ x) {
    long long gid = (long long)blockIdx.x * 256 + threadIdx.x;   // over KNELEM/4
    long long i = gid * 4;
    float4 v = *reinterpret_cast<const float4*>(x + i);
    __half2 p0 = __floats2half2_rn(v.x, v.y);
    __half2 p1 = __floats2half2_rn(v.z, v.w);
    uint2 out;
    out.x = *reinterpret_cast<uint32_t*>(&p0);
    out.y = *reinterpret_cast<uint32_t*>(&p1);
    *reinterpret_cast<uint2*>(&g_ah[i]) = out;
}

// ---------------- kernel 3: pipelined fp16 mma.sync GEMM (128x128 CTA, 64x32 warp, 2 CTA/SM) ----------------
// C = sum over 24 chunks: chunk kc: A offset = (kc<12 ? kc : kc-12)*64 over width 768
//                                   B offset = kc*64 over width 1536  ([Wh | Wl])
__global__ __launch_bounds__(256, 2) void gemm_kernel(
    const __half* __restrict__ A, const __half* __restrict__ B,
    const float* __restrict__ bias, float* __restrict__ C, int ldc) {
    extern __shared__ char smem[];
    const uint32_t sb = smem_u32(smem);
    const int tid = threadIdx.x, lane = tid & 31, wid = tid >> 5;
    const int m0 = blockIdx.y * BM_;
    const int n0 = blockIdx.x * BN_;
    const int wm = (wid >> 2) * 64;     // 2 m-warps x 64
    const int wn = (wid & 3) * 32;      // 4 n-warps x 32

    const int arow = tid >> 3, acg = tid & 7;
    const __half* Abase = A + (size_t)m0 * KD_;
    const __half* Bbase = B + (size_t)n0 * KWST_;

    // ldmatrix lane constants
    const int a_row_l = wm + (lane & 15);
    const uint32_t a_xor = (uint32_t)(a_row_l & 7) << 4;
    const uint32_t a_k2 = (uint32_t)(lane >> 4) * 16;
    const int gq = lane >> 3;
    const int b_row_l = wn + (gq >> 1) * 8 + (lane & 7);
    const uint32_t b_xor = (uint32_t)(b_row_l & 7) << 4;
    const uint32_t b_k2 = (uint32_t)(gq & 1) * 16;

    float acc[4][4][4];
#pragma unroll
    for (int i = 0; i < 4; i++)
#pragma unroll
        for (int j = 0; j < 4; j++)
#pragma unroll
            for (int r = 0; r < 4; r++) acc[i][j][r] = 0.f;

#define LOAD_A_(st_, kc_)                                                           \
    {                                                                               \
        int k0_ = (((kc_) < 12) ? (kc_) : (kc_) - 12) * BK_;                        \
        _Pragma("unroll")                                                           \
        for (int it_ = 0; it_ < 4; it_++) {                                         \
            int row_ = arow + it_ * 32;                                             \
            uint32_t so_ = (st_) + (uint32_t)row_ * 128 +                           \
                           (((uint32_t)acg * 16) ^ ((uint32_t)(row_ & 7) << 4));    \
            cp_async16(so_, Abase + (size_t)row_ * KD_ + k0_ + acg * 8);            \
        }                                                                           \
    }
#define LOAD_B_(st_, kc_)                                                           \
    {                                                                               \
        int k0_ = (kc_) * BK_;                                                      \
        _Pragma("unroll")                                                           \
        for (int it_ = 0; it_ < 4; it_++) {                                         \
            int row_ = arow + it_ * 32;                                             \
            uint32_t so_ = (st_) + OFF_B_ + (uint32_t)row_ * 128 +                  \
                           (((uint32_t)acg * 16) ^ ((uint32_t)(row_ & 7) << 4));    \
            cp_async16(so_, Bbase + (size_t)row_ * KWST_ + k0_ + acg * 8);          \
        }                                                                           \
    }

    // prologue: stages 0..1
    LOAD_A_(sb, 0); LOAD_B_(sb, 0); CP_COMMIT_();
    LOAD_A_(sb + STAGE_BYTES_, 1); LOAD_B_(sb + STAGE_BYTES_, 1); CP_COMMIT_();

    uint32_t Af[2][4][4], Bf[2][4][2];

#define LOAD_FRAGS_(st, ks, buf)                                                    \
    {                                                                               \
        _Pragma("unroll")                                                           \
        for (int mf_ = 0; mf_ < 4; mf_++) {                                         \
            uint32_t ad_ = (st) + (uint32_t)(a_row_l + mf_ * 16) * 128 +            \
                           (((uint32_t)((ks) * 32) + a_k2) ^ a_xor);                \
            ldsm_x4(Af[buf][mf_][0], Af[buf][mf_][1], Af[buf][mf_][2],              \
                    Af[buf][mf_][3], ad_);                                          \
        }                                                                           \
        _Pragma("unroll")                                                           \
        for (int np_ = 0; np_ < 2; np_++) {                                         \
            uint32_t bd_ = (st) + OFF_B_ + (uint32_t)(b_row_l + np_ * 16) * 128 +   \
                           (((uint32_t)((ks) * 32) + b_k2) ^ b_xor);                \
            uint32_t r0_, r1_, r2_, r3_;                                            \
            ldsm_x4(r0_, r1_, r2_, r3_, bd_);                                       \
            Bf[buf][np_ * 2][0] = r0_; Bf[buf][np_ * 2][1] = r1_;                   \
            Bf[buf][np_ * 2 + 1][0] = r2_; Bf[buf][np_ * 2 + 1][1] = r3_;           \
        }                                                                           \
    }

    // wait stage 0, preload its ks0 fragments
    CP_WAIT_(1);
    __syncthreads();
    LOAD_FRAGS_(sb, 0, 0);

    const uint32_t stage_off[3] = {0u, STAGE_BYTES_, 2u * STAGE_BYTES_};
    int cur = 0;                 // stage index of kc
    for (int kc = 0; kc < KITERS_; kc++) {
        const uint32_t st = sb + stage_off[cur];
        int ldstage = cur + 2; if (ldstage >= 3) ldstage -= 3;
        const uint32_t lst = sb + stage_off[ldstage];
        int nxt = cur + 1; if (nxt >= 3) nxt -= 3;
        const int ld = kc + 2;
        const bool doload = ld < KITERS_;
#pragma unroll
        for (int ks = 0; ks < 4; ks++) {
            if (ks == 0 && doload) { LOAD_A_(lst, ld); }
            if (ks == 1 && doload) { LOAD_B_(lst, ld); }
            if (ks == 1) { CP_COMMIT_(); }
            if (ks == 3) {
                if (kc + 1 < KITERS_) {
                    CP_WAIT_(1);
                    __syncthreads();
                    LOAD_FRAGS_(sb + stage_off[nxt], 0, 0);
                }
            } else {
                LOAD_FRAGS_(st, ks + 1, (ks + 1) & 1);
            }
#pragma unroll
            for (int mf = 0; mf < 4; mf++)
#pragma unroll
                for (int nf = 0; nf < 4; nf++)
                    mma_f16(acc[mf][nf], Af[ks & 1][mf], Bf[ks & 1][nf]);
        }
        cur = nxt;
    }

    // epilogue: fp32 stores + bias
    const int crow0 = m0 + wm + (lane >> 2);
    const int ccol0 = n0 + wn + (lane & 3) * 2;
#pragma unroll
    for (int mf = 0; mf < 4; mf++) {
#pragma unroll
        for (int nf = 0; nf < 4; nf++) {
            int col = ccol0 + nf * 8;
            float b0 = bias[col], b1 = bias[col + 1];
            int r0 = crow0 + mf * 16;
            float2 v0 = make_float2(acc[mf][nf][0] + b0, acc[mf][nf][1] + b1);
            float2 v1 = make_float2(acc[mf][nf][2] + b0, acc[mf][nf][3] + b1);
            *reinterpret_cast<float2*>(C + (size_t)r0 * ldc + col) = v0;
            *reinterpret_cast<float2*>(C + (size_t)(r0 + 8) * ldc + col) = v1;
        }
    }
#undef LOAD_A_
#undef LOAD_B_
#undef LOAD_FRAGS_
}

// ---------------- kernel 4: 3-tap local attention (warp per token x head-pair) ----------------
__global__ __launch_bounds__(256) void local_attn_kernel() {
    int gw = (blockIdx.x * 256 + threadIdx.x) >> 5;      // KBT_*6 warps
    int lid = threadIdx.x & 31;
    int token = gw / 6;
    int hp = gw - token * 6;
    int t = token & (KT_ - 1);
    size_t base = (size_t)token * KNQKV_ + hp * 128 + lid * 4;  // q at +0, k +768, v +1536

    float4 q = *reinterpret_cast<const float4*>(&g_qkv[base]);

    float sc[3];
#pragma unroll
    for (int j = 0; j < 3; j++) {
        int off = (j - 1) * KINT_;
        bool valid = ((unsigned)(t + off) < (unsigned)KT_);
        float p = 0.f;
        if (valid) {
            const float4 k = *reinterpret_cast<const float4*>(
                &g_qkv[base + (long long)off * KNQKV_ + 768]);
            p = q.x * k.x + q.y * k.y + q.z * k.z + q.w * k.w;
        }
#pragma unroll
        for (int m = 8; m; m >>= 1) p += __shfl_xor_sync(0xffffffffu, p, m);
        sc[j] = valid ? p * 0.125f : -INFINITY;          // 1/sqrt(64)
    }
    float mx = fmaxf(sc[0], fmaxf(sc[1], sc[2]));
    float e[3], den = 0.f;
#pragma unroll
    for (int j = 0; j < 3; j++) { e[j] = __expf(sc[j] - mx); den += e[j]; }
    float rden = 1.f / den;

    float a0 = 0.f, a1 = 0.f, a2 = 0.f, a3 = 0.f;
#pragma unroll
    for (int j = 0; j < 3; j++) {
        int off = (j - 1) * KINT_;
        if ((unsigned)(t + off) < (unsigned)KT_) {
            const float4 v = *reinterpret_cast<const float4*>(
                &g_qkv[base + (long long)off * KNQKV_ + 1536]);
            float w = e[j] * rden;
            a0 += w * v.x; a1 += w * v.y; a2 += w * v.z; a3 += w * v.w;
        }
    }
    __half2 p0 = __floats2half2_rn(a0, a1);
    __half2 p1 = __floats2half2_rn(a2, a3);
    uint2 out;
    out.x = *reinterpret_cast<uint32_t*>(&p0);
    out.y = *reinterpret_cast<uint32_t*>(&p1);
    size_t base2 = (size_t)token * KD_ + hp * 128 + lid * 4;
    *reinterpret_cast<uint2*>(&g_ah[base2]) = out;
}

// ---------------- kernel 5: residual + LayerNorm ----------------
__global__ __launch_bounds__(256) void ln_kernel(
    const float* __restrict__ x, const float* __restrict__ gamma,
    const float* __restrict__ beta, float* __restrict__ out) {
    __shared__ float s_sum[8], s_sq[8];
    int r = blockIdx.x, tid = threadIdx.x, wid = tid >> 5, lid = tid & 31;
    size_t base = (size_t)r * KD_;

    float y[3], s = 0.f, s2 = 0.f;
#pragma unroll
    for (int i = 0; i < 3; i++) {
        int c = tid + i * 256;
        float v = g_o[base + c] + x[base + c];
        y[i] = v; s += v; s2 += v * v;
    }
#pragma unroll
    for (int m = 16; m; m >>= 1) {
        s  += __shfl_xor_sync(0xffffffffu, s, m);
        s2 += __shfl_xor_sync(0xffffffffu, s2, m);
    }
    if (lid == 0) { s_sum[wid] = s; s_sq[wid] = s2; }
    __syncthreads();
    float ts = 0.f, ts2 = 0.f;
#pragma unroll
    for (int i = 0; i < 8; i++) { ts += s_sum[i]; ts2 += s_sq[i]; }
    float mean = ts * (1.f / KD_);
    float var  = ts2 * (1.f / KD_) - mean * mean;
    float inv  = rsqrtf(var + 1e-5f);
#pragma unroll
    for (int i = 0; i < 3; i++) {
        int c = tid + i * 256;
        out[base + c] = (y[i] - mean) * inv * gamma[c] + beta[c];
    }
}

// ---------------- launch ----------------
extern "C" void kernel_launch(void* const* d_in, const int* in_sizes, int n_in,
                              void* d_out, int out_size) {
    const float* x     = (const float*)d_in[0];
    const float* Wq    = (const float*)d_in[1];
    const float* bq    = (const float*)d_in[2];
    const float* Wk    = (const float*)d_in[3];
    const float* bk    = (const float*)d_in[4];
    const float* Wv    = (const float*)d_in[5];
    const float* bv    = (const float*)d_in[6];
    const float* Wo    = (const float*)d_in[7];
    const float* bo    = (const float*)d_in[8];
    const float* gamma = (const float*)d_in[9];
    const float* beta  = (const float*)d_in[10];

    void *p_ah, *p_w2, *p_qkv, *p_o, *p_bqkv;
    cudaGetSymbolAddress(&p_ah,  g_ah);
    cudaGetSymbolAddress(&p_w2,  g_w2);
    cudaGetSymbolAddress(&p_qkv, g_qkv);
    cudaGetSymbolAddress(&p_o,   g_o);
    cudaGetSymbolAddress(&p_bqkv, g_bqkv);

    const __half* ah = (const __half*)p_ah;
    const __half* w2 = (const __half*)p_w2;
    const size_t WSTRIDE = (size_t)KD_ * KWST_;

    cudaFuncSetAttribute(gemm_kernel,
                         cudaFuncAttributeMaxDynamicSharedMemorySize, (int)SMEM_BYTES_);

    prep_weights_kernel<<<WELEM_ / 256, 256>>>(Wq, Wk, Wv, Wo, bq, bk, bv);
    split_x_kernel<<<(int)(KNELEM_ / 4 / 256), 256>>>(x);

    // fused QKV: C[32768, 2304]
    dim3 gqkv(KNQKV_ / BN_, KBT_ / BM_);   // (18, 256)
    gemm_kernel<<<gqkv, 256, SMEM_BYTES_>>>(ah, w2, (const float*)p_bqkv,
                                            (float*)p_qkv, KNQKV_);
    // attention: 32768 tokens * 6 head-pairs = 196608 warps = 24576 blocks
    local_attn_kernel<<<KBT_ * 6 / 8, 256>>>();
    // O projection: C[32768, 768]
    dim3 go(KD_ / BN_, KBT_ / BM_);        // (6, 256)
    gemm_kernel<<<go, 256, SMEM_BYTES_>>>(ah, w2 + 3 * WSTRIDE, bo, (float*)p_o, KD_);
    ln_kernel<<<KBT_, 256>>>(x, gamma, beta, (float*)d_out);
}

// round 14
// speedup vs baseline: 1.3154x; 1.0039x over previous
#include <cuda_runtime.h>
#include <cuda_fp16.h>
#include <cstdint>
#include <math.h>

// ---------------- problem constants ----------------
#define KB_   8
#define KT_   4096
#define KD_   768
#define KH_   12
#define KHD_  64
#define KINT_ 3
#define KBT_  (KB_ * KT_)                 // 32768
#define KNELEM_ ((size_t)KBT_ * KD_)      // 25165824
#define KWST_ 1536                        // weight stored K width: [Wh(768) | Wl(768)]
#define KNQKV_ 2304                       // Wq|Wk|Wv stacked along N
#define WELEM_ (KD_ * KD_)

// GEMM tiling: 128x128 CTA, 64x32 warp, 3 stages -> 2 CTAs/SM
#define BM_ 128
#define BN_ 128
#define BK_ 64
#define KITERS_ 24                        // hh(12) + hl(12) chunk schedule (fp16 2-term)
#define STAGES_ 3
#define STAGE_BYTES_ 32768u               // A 16KB + B 16KB
#define OFF_B_ 16384u
#define SMEM_BYTES_ (STAGES_ * STAGE_BYTES_)   // 98304

// ---------------- device scratch ----------------
__device__ __half g_ah[KNELEM_];                             // fp16 activations (x, then attn)
__device__ __half g_w2[4 * (size_t)KD_ * KWST_];             // fp16 split weights [Wh|Wl]
__device__ float g_bqkv[KNQKV_];                             // concat bias q|k|v
__device__ __half g_qkvh[(size_t)KBT_ * KNQKV_];             // fused QKV output (fp16)
__device__ float g_o[KNELEM_];                               // y = o + bias + residual

// ---------------- helpers ----------------
__device__ __forceinline__ uint32_t smem_u32(const void* p) {
    return (uint32_t)__cvta_generic_to_shared(p);
}

__device__ __forceinline__ void cp_async16(uint32_t saddr, const void* gaddr) {
    asm volatile("cp.async.cg.shared.global [%0], [%1], 16;" :: "r"(saddr), "l"(gaddr));
}
#define CP_COMMIT_()  asm volatile("cp.async.commit_group;" ::: "memory")
#define CP_WAIT_(n)   asm volatile("cp.async.wait_group %0;" :: "n"(n) : "memory")

__device__ __forceinline__ void ldsm_x4(uint32_t& r0, uint32_t& r1, uint32_t& r2, uint32_t& r3,
                                        uint32_t addr) {
    asm volatile("ldmatrix.sync.aligned.m8n8.x4.shared.b16 {%0,%1,%2,%3}, [%4];"
                 : "=r"(r0), "=r"(r1), "=r"(r2), "=r"(r3) : "r"(addr));
}

__device__ __forceinline__ void mma_f16(float* c, const uint32_t* a, const uint32_t* b) {
    asm volatile(
        "mma.sync.aligned.m16n8k16.row.col.f32.f16.f16.f32 "
        "{%0,%1,%2,%3}, {%4,%5,%6,%7}, {%8,%9}, {%0,%1,%2,%3};"
        : "+f"(c[0]), "+f"(c[1]), "+f"(c[2]), "+f"(c[3])
        : "r"(a[0]), "r"(a[1]), "r"(a[2]), "r"(a[3]), "r"(b[0]), "r"(b[1]));
}

// ---------------- kernel 1: transpose + fp16-split weights, concat bias ----------------
__global__ __launch_bounds__(256) void prep_weights_kernel(
    const float* __restrict__ Wq, const float* __restrict__ Wk,
    const float* __restrict__ Wv, const float* __restrict__ Wo,
    const float* __restrict__ bq, const float* __restrict__ bk,
    const float* __restrict__ bv) {
    int idx = blockIdx.x * 256 + threadIdx.x;       // over D*D
    int n = idx / KD_;
    int k = idx - n * KD_;
    const float* Ws[4] = {Wq, Wk, Wv, Wo};
#pragma unroll
    for (int w = 0; w < 4; w++) {
        float val = Ws[w][(size_t)k * KD_ + n];     // W[k][n] -> B[n][k]
        __half hi = __float2half(val);
        __half lo = __float2half(val - __half2float(hi));
        size_t base = (size_t)w * KD_ * KWST_ + (size_t)n * KWST_;
        g_w2[base + k]       = hi;
        g_w2[base + 768 + k] = lo;
    }
    if (idx < KNQKV_) {
        g_bqkv[idx] = (idx < 768) ? bq[idx] : (idx < 1536) ? bk[idx - 768] : bv[idx - 1536];
    }
}

// ---------------- kernel 2: convert x -> fp16 ----------------
__global__ __launch_bounds__(256) void split_x_kernel(const float* __restrict__ x) {
    long long gid = (long long)blockIdx.x * 256 + threadIdx.x;   // over KNELEM/4
    long long i = gid * 4;
    float4 v = *reinterpret_cast<const float4*>(x + i);
    __half2 p0 = __floats2half2_rn(v.x, v.y);
    __half2 p1 = __floats2half2_rn(v.z, v.w);
    uint2 out;
    out.x = *reinterpret_cast<uint32_t*>(&p0);
    out.y = *reinterpret_cast<uint32_t*>(&p1);
    *reinterpret_cast<uint2*>(&g_ah[i]) = out;
}

// ---------------- kernel 3: pipelined fp16 mma.sync GEMM ----------------
// C = sum over 24 chunks: chunk kc: A offset = (kc<12 ? kc : kc-12)*64 over width 768
//                                   B offset = kc*64 over width 1536  ([Wh | Wl])
// HALF_OUT: store fp16 (QKV path). else: store fp32 with fused residual (O path).
template <bool HALF_OUT>
__global__ __launch_bounds__(256, 2) void gemm_kernel(
    const __half* __restrict__ A, const __half* __restrict__ B,
    const float* __restrict__ bias, void* __restrict__ Cout, int ldc,
    const float* __restrict__ resid) {
    extern __shared__ char smem[];
    const uint32_t sb = smem_u32(smem);
    const int tid = threadIdx.x, lane = tid & 31, wid = tid >> 5;
    const int m0 = blockIdx.y * BM_;
    const int n0 = blockIdx.x * BN_;
    const int wm = (wid >> 2) * 64;     // 2 m-warps x 64
    const int wn = (wid & 3) * 32;      // 4 n-warps x 32

    const int arow = tid >> 3, acg = tid & 7;
    const __half* Abase = A + (size_t)m0 * KD_;
    const __half* Bbase = B + (size_t)n0 * KWST_;

    // ldmatrix lane constants
    const int a_row_l = wm + (lane & 15);
    const uint32_t a_xor = (uint32_t)(a_row_l & 7) << 4;
    const uint32_t a_k2 = (uint32_t)(lane >> 4) * 16;
    const int gq = lane >> 3;
    const int b_row_l = wn + (gq >> 1) * 8 + (lane & 7);
    const uint32_t b_xor = (uint32_t)(b_row_l & 7) << 4;
    const uint32_t b_k2 = (uint32_t)(gq & 1) * 16;

    float acc[4][4][4];
#pragma unroll
    for (int i = 0; i < 4; i++)
#pragma unroll
        for (int j = 0; j < 4; j++)
#pragma unroll
            for (int r = 0; r < 4; r++) acc[i][j][r] = 0.f;

#define LOAD_A_(st_, kc_)                                                           \
    {                                                                               \
        int k0_ = (((kc_) < 12) ? (kc_) : (kc_) - 12) * BK_;                        \
        _Pragma("unroll")                                                           \
        for (int it_ = 0; it_ < 4; it_++) {                                         \
            int row_ = arow + it_ * 32;                                             \
            uint32_t so_ = (st_) + (uint32_t)row_ * 128 +                           \
                           (((uint32_t)acg * 16) ^ ((uint32_t)(row_ & 7) << 4));    \
            cp_async16(so_, Abase + (size_t)row_ * KD_ + k0_ + acg * 8);            \
        }                                                                           \
    }
#define LOAD_B_(st_, kc_)                                                           \
    {                                                                               \
        int k0_ = (kc_) * BK_;                                                      \
        _Pragma("unroll")                                                           \
        for (int it_ = 0; it_ < 4; it_++) {                                         \
            int row_ = arow + it_ * 32;                                             \
            uint32_t so_ = (st_) + OFF_B_ + (uint32_t)row_ * 128 +                  \
                           (((uint32_t)acg * 16) ^ ((uint32_t)(row_ & 7) << 4));    \
            cp_async16(so_, Bbase + (size_t)row_ * KWST_ + k0_ + acg * 8);          \
        }                                                                           \
    }

    // prologue: stages 0..1
    LOAD_A_(sb, 0); LOAD_B_(sb, 0); CP_COMMIT_();
    LOAD_A_(sb + STAGE_BYTES_, 1); LOAD_B_(sb + STAGE_BYTES_, 1); CP_COMMIT_();

    uint32_t Af[2][4][4], Bf[2][4][2];

#define LOAD_FRAGS_(st, ks, buf)                                                    \
    {                                                                               \
        _Pragma("unroll")                                                           \
        for (int mf_ = 0; mf_ < 4; mf_++) {                                         \
            uint32_t ad_ = (st) + (uint32_t)(a_row_l + mf_ * 16) * 128 +            \
                           (((uint32_t)((ks) * 32) + a_k2) ^ a_xor);                \
            ldsm_x4(Af[buf][mf_][0], Af[buf][mf_][1], Af[buf][mf_][2],              \
                    Af[buf][mf_][3], ad_);                                          \
        }                                                                           \
        _Pragma("unroll")                                                           \
        for (int np_ = 0; np_ < 2; np_++) {                                         \
            uint32_t bd_ = (st) + OFF_B_ + (uint32_t)(b_row_l + np_ * 16) * 128 +   \
                           (((uint32_t)((ks) * 32) + b_k2) ^ b_xor);                \
            uint32_t r0_, r1_, r2_, r3_;                                            \
            ldsm_x4(r0_, r1_, r2_, r3_, bd_);                                       \
            Bf[buf][np_ * 2][0] = r0_; Bf[buf][np_ * 2][1] = r1_;                   \
            Bf[buf][np_ * 2 + 1][0] = r2_; Bf[buf][np_ * 2 + 1][1] = r3_;           \
        }                                                                           \
    }

    // wait stage 0, preload its ks0 fragments
    CP_WAIT_(1);
    __syncthreads();
    LOAD_FRAGS_(sb, 0, 0);

    const uint32_t stage_off[3] = {0u, STAGE_BYTES_, 2u * STAGE_BYTES_};
    int cur = 0;                 // stage index of kc
    for (int kc = 0; kc < KITERS_; kc++) {
        const uint32_t st = sb + stage_off[cur];
        int ldstage = cur + 2; if (ldstage >= 3) ldstage -= 3;
        const uint32_t lst = sb + stage_off[ldstage];
        int nxt = cur + 1; if (nxt >= 3) nxt -= 3;
        const int ld = kc + 2;
        const bool doload = ld < KITERS_;
#pragma unroll
        for (int ks = 0; ks < 4; ks++) {
            if (ks == 0 && doload) { LOAD_A_(lst, ld); }
            if (ks == 1 && doload) { LOAD_B_(lst, ld); }
            if (ks == 1) { CP_COMMIT_(); }
            if (ks == 3) {
                if (kc + 1 < KITERS_) {
                    CP_WAIT_(1);
                    __syncthreads();
                    LOAD_FRAGS_(sb + stage_off[nxt], 0, 0);
                }
            } else {
                LOAD_FRAGS_(st, ks + 1, (ks + 1) & 1);
            }
#pragma unroll
            for (int mf = 0; mf < 4; mf++)
#pragma unroll
                for (int nf = 0; nf < 4; nf++)
                    mma_f16(acc[mf][nf], Af[ks & 1][mf], Bf[ks & 1][nf]);
        }
        cur = nxt;
    }

    // epilogue
    const int crow0 = m0 + wm + (lane >> 2);
    const int ccol0 = n0 + wn + (lane & 3) * 2;
#pragma unroll
    for (int mf = 0; mf < 4; mf++) {
#pragma unroll
        for (int nf = 0; nf < 4; nf++) {
            int col = ccol0 + nf * 8;
            float b0 = bias[col], b1 = bias[col + 1];
            int r0 = crow0 + mf * 16;
            if (HALF_OUT) {
                __half* C = (__half*)Cout;
                __half2 h0 = __floats2half2_rn(acc[mf][nf][0] + b0, acc[mf][nf][1] + b1);
                __half2 h1 = __floats2half2_rn(acc[mf][nf][2] + b0, acc[mf][nf][3] + b1);
                *reinterpret_cast<uint32_t*>(C + (size_t)r0 * ldc + col) =
                    *reinterpret_cast<uint32_t*>(&h0);
                *reinterpret_cast<uint32_t*>(C + (size_t)(r0 + 8) * ldc + col) =
                    *reinterpret_cast<uint32_t*>(&h1);
            } else {
                float* C = (float*)Cout;
                float2 rx0 = *reinterpret_cast<const float2*>(resid + (size_t)r0 * ldc + col);
                float2 rx1 = *reinterpret_cast<const float2*>(resid + (size_t)(r0 + 8) * ldc + col);
                float2 v0 = make_float2(acc[mf][nf][0] + b0 + rx0.x, acc[mf][nf][1] + b1 + rx0.y);
                float2 v1 = make_float2(acc[mf][nf][2] + b0 + rx1.x, acc[mf][nf][3] + b1 + rx1.y);
                *reinterpret_cast<float2*>(C + (size_t)r0 * ldc + col) = v0;
                *reinterpret_cast<float2*>(C + (size_t)(r0 + 8) * ldc + col) = v1;
            }
        }
    }
#undef LOAD_A_
#undef LOAD_B_
#undef LOAD_FRAGS_
}

// ---------------- kernel 4: 3-tap local attention (warp per token x head-pair, fp16 qkv) ----------------
__global__ __launch_bounds__(256) void local_attn_kernel() {
    int gw = (blockIdx.x * 256 + threadIdx.x) >> 5;      // KBT_*6 warps
    int lid = threadIdx.x & 31;
    int token = gw / 6;
    int hp = gw - token * 6;
    int t = token & (KT_ - 1);
    size_t base = (size_t)token * KNQKV_ + hp * 128 + lid * 4;  // q at +0, k +768, v +1536

    uint2 qu = *reinterpret_cast<const uint2*>(&g_qkvh[base]);
    float2 q01 = __half22float2(*reinterpret_cast<__half2*>(&qu.x));
    float2 q23 = __half22float2(*reinterpret_cast<__half2*>(&qu.y));

    float sc[3];
#pragma unroll
    for (int j = 0; j < 3; j++) {
        int off = (j - 1) * KINT_;
        bool valid = ((unsigned)(t + off) < (unsigned)KT_);
        float p = 0.f;
        if (valid) {
            uint2 ku = *reinterpret_cast<const uint2*>(
                &g_qkvh[base + (long long)off * KNQKV_ + 768]);
            float2 k01 = __half22float2(*reinterpret_cast<__half2*>(&ku.x));
            float2 k23 = __half22float2(*reinterpret_cast<__half2*>(&ku.y));
            p = q01.x * k01.x + q01.y * k01.y + q23.x * k23.x + q23.y * k23.y;
        }
#pragma unroll
        for (int m = 8; m; m >>= 1) p += __shfl_xor_sync(0xffffffffu, p, m);
        sc[j] = valid ? p * 0.125f : -INFINITY;          // 1/sqrt(64)
    }
    float mx = fmaxf(sc[0], fmaxf(sc[1], sc[2]));
    float e[3], den = 0.f;
#pragma unroll
    for (int j = 0; j < 3; j++) { e[j] = __expf(sc[j] - mx); den += e[j]; }
    float rden = 1.f / den;

    float a0 = 0.f, a1 = 0.f, a2 = 0.f, a3 = 0.f;
#pragma unroll
    for (int j = 0; j < 3; j++) {
        int off = (j - 1) * KINT_;
        if ((unsigned)(t + off) < (unsigned)KT_) {
            uint2 vu = *reinterpret_cast<const uint2*>(
                &g_qkvh[base + (long long)off * KNQKV_ + 1536]);
            float2 v01 = __half22float2(*reinterpret_cast<__half2*>(&vu.x));
            float2 v23 = __half22float2(*reinterpret_cast<__half2*>(&vu.y));
            float w = e[j] * rden;
            a0 += w * v01.x; a1 += w * v01.y; a2 += w * v23.x; a3 += w * v23.y;
        }
    }
    __half2 p0 = __floats2half2_rn(a0, a1);
    __half2 p1 = __floats2half2_rn(a2, a3);
    uint2 out;
    out.x = *reinterpret_cast<uint32_t*>(&p0);
    out.y = *reinterpret_cast<uint32_t*>(&p1);
    size_t base2 = (size_t)token * KD_ + hp * 128 + lid * 4;
    *reinterpret_cast<uint2*>(&g_ah[base2]) = out;
}

// ---------------- kernel 5: LayerNorm over precomputed y ----------------
__global__ __launch_bounds__(256) void ln_kernel(
    const float* __restrict__ gamma, const float* __restrict__ beta,
    float* __restrict__ out) {
    __shared__ float s_sum[8], s_sq[8];
    int r = blockIdx.x, tid = threadIdx.x, wid = tid >> 5, lid = tid & 31;
    size_t base = (size_t)r * KD_;

    float y[3], s = 0.f, s2 = 0.f;
#pragma unroll
    for (int i = 0; i < 3; i++) {
        int c = tid + i * 256;
        float v = g_o[base + c];
        y[i] = v; s += v; s2 += v * v;
    }
#pragma unroll
    for (int m = 16; m; m >>= 1) {
        s  += __shfl_xor_sync(0xffffffffu, s, m);
        s2 += __shfl_xor_sync(0xffffffffu, s2, m);
    }
    if (lid == 0) { s_sum[wid] = s; s_sq[wid] = s2; }
    __syncthreads();
    float ts = 0.f, ts2 = 0.f;
#pragma unroll
    for (int i = 0; i < 8; i++) { ts += s_sum[i]; ts2 += s_sq[i]; }
    float mean = ts * (1.f / KD_);
    float var  = ts2 * (1.f / KD_) - mean * mean;
    float inv  = rsqrtf(var + 1e-5f);
#pragma unroll
    for (int i = 0; i < 3; i++) {
        int c = tid + i * 256;
        out[base + c] = (y[i] - mean) * inv * gamma[c] + beta[c];
    }
}

// ---------------- launch ----------------
extern "C" void kernel_launch(void* const* d_in, const int* in_sizes, int n_in,
                              void* d_out, int out_size) {
    const float* x     = (const float*)d_in[0];
    const float* Wq    = (const float*)d_in[1];
    const float* bq    = (const float*)d_in[2];
    const float* Wk    = (const float*)d_in[3];
    const float* bk    = (const float*)d_in[4];
    const float* Wv    = (const float*)d_in[5];
    const float* bv    = (const float*)d_in[6];
    const float* Wo    = (const float*)d_in[7];
    const float* bo    = (const float*)d_in[8];
    const float* gamma = (const float*)d_in[9];
    const float* beta  = (const float*)d_in[10];

    void *p_ah, *p_w2, *p_qkvh, *p_o, *p_bqkv;
    cudaGetSymbolAddress(&p_ah,   g_ah);
    cudaGetSymbolAddress(&p_w2,   g_w2);
    cudaGetSymbolAddress(&p_qkvh, g_qkvh);
    cudaGetSymbolAddress(&p_o,    g_o);
    cudaGetSymbolAddress(&p_bqkv, g_bqkv);

    const __half* ah = (const __half*)p_ah;
    const __half* w2 = (const __half*)p_w2;
    const size_t WSTRIDE = (size_t)KD_ * KWST_;

    cudaFuncSetAttribute(gemm_kernel<true>,
                         cudaFuncAttributeMaxDynamicSharedMemorySize, (int)SMEM_BYTES_);
    cudaFuncSetAttribute(gemm_kernel<false>,
                         cudaFuncAttributeMaxDynamicSharedMemorySize, (int)SMEM_BYTES_);

    prep_weights_kernel<<<WELEM_ / 256, 256>>>(Wq, Wk, Wv, Wo, bq, bk, bv);
    split_x_kernel<<<(int)(KNELEM_ / 4 / 256), 256>>>(x);

    // fused QKV: C[32768, 2304] fp16
    dim3 gqkv(KNQKV_ / BN_, KBT_ / BM_);   // (18, 256)
    gemm_kernel<true><<<gqkv, 256, SMEM_BYTES_>>>(ah, w2, (const float*)p_bqkv,
                                                  p_qkvh, KNQKV_, nullptr);
    // attention: 32768 tokens * 6 head-pairs = 196608 warps = 24576 blocks
    local_attn_kernel<<<KBT_ * 6 / 8, 256>>>();
    // O projection: C[32768, 768] fp32 with fused residual (y = o + bo + x)
    dim3 go(KD_ / BN_, KBT_ / BM_);        // (6, 256)
    gemm_kernel<false><<<go, 256, SMEM_BYTES_>>>(ah, w2 + 3 * WSTRIDE, bo,
                                                 p_o, KD_, x);
    ln_kernel<<<KBT_, 256>>>(gamma, beta, (float*)d_out);
}

// round 16
// speedup vs baseline: 2.3229x; 1.7659x over previous
#include <cuda_runtime.h>
#include <cuda_fp16.h>
#include <cstdint>
#include <math.h>

// ---------------- problem constants ----------------
#define KB_   8
#define KT_   4096
#define KD_   768
#define KH_   12
#define KHD_  64
#define KINT_ 3
#define KBT_  (KB_ * KT_)                 // 32768
#define KNELEM_ ((size_t)KBT_ * KD_)      // 25165824
#define KNQKV_ 2304                       // Wq|Wk|Wv stacked along N
#define WELEM_ (KD_ * KD_)

// GEMM tiling: 128x128 CTA, 64x32 warp, 3 stages -> 2 CTAs/SM
#define BM_ 128
#define BN_ 128
#define BK_ 64
#define KITERS_ 12                        // single-term fp16: K=768 = 12 x 64
#define STAGES_ 3
#define STAGE_BYTES_ 32768u               // A 16KB + B 16KB
#define OFF_B_ 16384u
#define SMEM_BYTES_ (STAGES_ * STAGE_BYTES_)   // 98304

// ---------------- device scratch ----------------
__device__ __half g_ah[KNELEM_];                             // fp16 activations (x, then attn)
__device__ __half g_wqkv[(size_t)KNQKV_ * KD_];              // fp16 [Wq;Wk;Wv]^T rows [n][k]
__device__ __half g_wo[(size_t)KD_ * KD_];                   // fp16 Wo^T [n][k]
__device__ float g_bqkv[KNQKV_];                             // concat bias q|k|v
__device__ __half g_qkvh[(size_t)KBT_ * KNQKV_];             // fused QKV output (fp16)
__device__ float g_o[KNELEM_];                               // y = o + bias + residual

// ---------------- helpers ----------------
__device__ __forceinline__ uint32_t smem_u32(const void* p) {
    return (uint32_t)__cvta_generic_to_shared(p);
}

__device__ __forceinline__ void cp_async16(uint32_t saddr, const void* gaddr) {
    asm volatile("cp.async.cg.shared.global [%0], [%1], 16;" :: "r"(saddr), "l"(gaddr));
}
#define CP_COMMIT_()  asm volatile("cp.async.commit_group;" ::: "memory")
#define CP_WAIT_(n)   asm volatile("cp.async.wait_group %0;" :: "n"(n) : "memory")

__device__ __forceinline__ void ldsm_x4(uint32_t& r0, uint32_t& r1, uint32_t& r2, uint32_t& r3,
                                        uint32_t addr) {
    asm volatile("ldmatrix.sync.aligned.m8n8.x4.shared.b16 {%0,%1,%2,%3}, [%4];"
                 : "=r"(r0), "=r"(r1), "=r"(r2), "=r"(r3) : "r"(addr));
}

__device__ __forceinline__ void mma_f16(float* c, const uint32_t* a, const uint32_t* b) {
    asm volatile(
        "mma.sync.aligned.m16n8k16.row.col.f32.f16.f16.f32 "
        "{%0,%1,%2,%3}, {%4,%5,%6,%7}, {%8,%9}, {%0,%1,%2,%3};"
        : "+f"(c[0]), "+f"(c[1]), "+f"(c[2]), "+f"(c[3])
        : "r"(a[0]), "r"(a[1]), "r"(a[2]), "r"(a[3]), "r"(b[0]), "r"(b[1]));
}

// ---------------- kernel 1: transpose weights -> fp16, concat bias ----------------
__global__ __launch_bounds__(256) void prep_weights_kernel(
    const float* __restrict__ Wq, const float* __restrict__ Wk,
    const float* __restrict__ Wv, const float* __restrict__ Wo,
    const float* __restrict__ bq, const float* __restrict__ bk,
    const float* __restrict__ bv) {
    int idx = blockIdx.x * 256 + threadIdx.x;       // over D*D
    int n = idx / KD_;
    int k = idx - n * KD_;
    g_wqkv[(size_t)n * KD_ + k]                    = __float2half(Wq[(size_t)k * KD_ + n]);
    g_wqkv[(size_t)(768 + n) * KD_ + k]            = __float2half(Wk[(size_t)k * KD_ + n]);
    g_wqkv[(size_t)(1536 + n) * KD_ + k]           = __float2half(Wv[(size_t)k * KD_ + n]);
    g_wo[(size_t)n * KD_ + k]                      = __float2half(Wo[(size_t)k * KD_ + n]);
    if (idx < KNQKV_) {
        g_bqkv[idx] = (idx < 768) ? bq[idx] : (idx < 1536) ? bk[idx - 768] : bv[idx - 1536];
    }
}

// ---------------- kernel 2: convert x -> fp16 ----------------
__global__ __launch_bounds__(256) void split_x_kernel(const float* __restrict__ x) {
    long long gid = (long long)blockIdx.x * 256 + threadIdx.x;   // over KNELEM/4
    long long i = gid * 4;
    float4 v = *reinterpret_cast<const float4*>(x + i);
    __half2 p0 = __floats2half2_rn(v.x, v.y);
    __half2 p1 = __floats2half2_rn(v.z, v.w);
    uint2 out;
    out.x = *reinterpret_cast<uint32_t*>(&p0);
    out.y = *reinterpret_cast<uint32_t*>(&p1);
    *reinterpret_cast<uint2*>(&g_ah[i]) = out;
}

// ---------------- kernel 3: pipelined fp16 mma.sync GEMM (single-term) ----------------
// C[M, ldc] = A[M,768] * B[ldc,768]^T + bias ; HALF_OUT: fp16 store, else fp32 + residual
template <bool HALF_OUT>
__global__ __launch_bounds__(256, 2) void gemm_kernel(
    const __half* __restrict__ A, const __half* __restrict__ B,
    const float* __restrict__ bias, void* __restrict__ Cout, int ldc,
    const float* __restrict__ resid) {
    extern __shared__ char smem[];
    const uint32_t sb = smem_u32(smem);
    const int tid = threadIdx.x, lane = tid & 31, wid = tid >> 5;
    const int m0 = blockIdx.y * BM_;
    const int n0 = blockIdx.x * BN_;
    const int wm = (wid >> 2) * 64;     // 2 m-warps x 64
    const int wn = (wid & 3) * 32;      // 4 n-warps x 32

    const int arow = tid >> 3, acg = tid & 7;
    const __half* Abase = A + (size_t)m0 * KD_;
    const __half* Bbase = B + (size_t)n0 * KD_;

    // ldmatrix lane constants
    const int a_row_l = wm + (lane & 15);
    const uint32_t a_xor = (uint32_t)(a_row_l & 7) << 4;
    const uint32_t a_k2 = (uint32_t)(lane >> 4) * 16;
    const int gq = lane >> 3;
    const int b_row_l = wn + (gq >> 1) * 8 + (lane & 7);
    const uint32_t b_xor = (uint32_t)(b_row_l & 7) << 4;
    const uint32_t b_k2 = (uint32_t)(gq & 1) * 16;

    float acc[4][4][4];
#pragma unroll
    for (int i = 0; i < 4; i++)
#pragma unroll
        for (int j = 0; j < 4; j++)
#pragma unroll
            for (int r = 0; r < 4; r++) acc[i][j][r] = 0.f;

#define LOAD_A_(st_, kc_)                                                           \
    {                                                                               \
        int k0_ = (kc_) * BK_;                                                      \
        _Pragma("unroll")                                                           \
        for (int it_ = 0; it_ < 4; it_++) {                                         \
            int row_ = arow + it_ * 32;                                             \
            uint32_t so_ = (st_) + (uint32_t)row_ * 128 +                           \
                           (((uint32_t)acg * 16) ^ ((uint32_t)(row_ & 7) << 4));    \
            cp_async16(so_, Abase + (size_t)row_ * KD_ + k0_ + acg * 8);            \
        }                                                                           \
    }
#define LOAD_B_(st_, kc_)                                                           \
    {                                                                               \
        int k0_ = (kc_) * BK_;                                                      \
        _Pragma("unroll")                                                           \
        for (int it_ = 0; it_ < 4; it_++) {                                         \
            int row_ = arow + it_ * 32;                                             \
            uint32_t so_ = (st_) + OFF_B_ + (uint32_t)row_ * 128 +                  \
                           (((uint32_t)acg * 16) ^ ((uint32_t)(row_ & 7) << 4));    \
            cp_async16(so_, Bbase + (size_t)row_ * KD_ + k0_ + acg * 8);            \
        }                                                                           \
    }

    // prologue: stages 0..1
    LOAD_A_(sb, 0); LOAD_B_(sb, 0); CP_COMMIT_();
    LOAD_A_(sb + STAGE_BYTES_, 1); LOAD_B_(sb + STAGE_BYTES_, 1); CP_COMMIT_();

    uint32_t Af[2][4][4], Bf[2][4][2];

#define LOAD_FRAGS_(st, ks, buf)                                                    \
    {                                                                               \
        _Pragma("unroll")                                                           \
        for (int mf_ = 0; mf_ < 4; mf_++) {                                         \
            uint32_t ad_ = (st) + (uint32_t)(a_row_l + mf_ * 16) * 128 +            \
                           (((uint32_t)((ks) * 32) + a_k2) ^ a_xor);                \
            ldsm_x4(Af[buf][mf_][0], Af[buf][mf_][1], Af[buf][mf_][2],              \
                    Af[buf][mf_][3], ad_);                                          \
        }                                                                           \
        _Pragma("unroll")                                                           \
        for (int np_ = 0; np_ < 2; np_++) {                                         \
            uint32_t bd_ = (st) + OFF_B_ + (uint32_t)(b_row_l + np_ * 16) * 128 +   \
                           (((uint32_t)((ks) * 32) + b_k2) ^ b_xor);                \
            uint32_t r0_, r1_, r2_, r3_;                                            \
            ldsm_x4(r0_, r1_, r2_, r3_, bd_);                                       \
            Bf[buf][np_ * 2][0] = r0_; Bf[buf][np_ * 2][1] = r1_;                   \
            Bf[buf][np_ * 2 + 1][0] = r2_; Bf[buf][np_ * 2 + 1][1] = r3_;           \
        }                                                                           \
    }

    // wait stage 0, preload its ks0 fragments
    CP_WAIT_(1);
    __syncthreads();
    LOAD_FRAGS_(sb, 0, 0);

    const uint32_t stage_off[3] = {0u, STAGE_BYTES_, 2u * STAGE_BYTES_};
    int cur = 0;                 // stage index of kc
    for (int kc = 0; kc < KITERS_; kc++) {
        const uint32_t st = sb + stage_off[cur];
        int ldstage = cur + 2; if (ldstage >= 3) ldstage -= 3;
        const uint32_t lst = sb + stage_off[ldstage];
        int nxt = cur + 1; if (nxt >= 3) nxt -= 3;
        const int ld = kc + 2;
        const bool doload = ld < KITERS_;
#pragma unroll
        for (int ks = 0; ks < 4; ks++) {
            if (ks == 0 && doload) { LOAD_A_(lst, ld); }
            if (ks == 1 && doload) { LOAD_B_(lst, ld); }
            if (ks == 1) { CP_COMMIT_(); }
            if (ks == 3) {
                if (kc + 1 < KITERS_) {
                    CP_WAIT_(1);
                    __syncthreads();
                    LOAD_FRAGS_(sb + stage_off[nxt], 0, 0);
                }
            } else {
                LOAD_FRAGS_(st, ks + 1, (ks + 1) & 1);
            }
#pragma unroll
            for (int mf = 0; mf < 4; mf++)
#pragma unroll
                for (int nf = 0; nf < 4; nf++)
                    mma_f16(acc[mf][nf], Af[ks & 1][mf], Bf[ks & 1][nf]);
        }
        cur = nxt;
    }

    // epilogue
    const int crow0 = m0 + wm + (lane >> 2);
    const int ccol0 = n0 + wn + (lane & 3) * 2;
#pragma unroll
    for (int mf = 0; mf < 4; mf++) {
#pragma unroll
        for (int nf = 0; nf < 4; nf++) {
            int col = ccol0 + nf * 8;
            float b0 = bias[col], b1 = bias[col + 1];
            int r0 = crow0 + mf * 16;
            if (HALF_OUT) {
                __half* C = (__half*)Cout;
                __half2 h0 = __floats2half2_rn(acc[mf][nf][0] + b0, acc[mf][nf][1] + b1);
                __half2 h1 = __floats2half2_rn(acc[mf][nf][2] + b0, acc[mf][nf][3] + b1);
                *reinterpret_cast<uint32_t*>(C + (size_t)r0 * ldc + col) =
                    *reinterpret_cast<uint32_t*>(&h0);
                *reinterpret_cast<uint32_t*>(C + (size_t)(r0 + 8) * ldc + col) =
                    *reinterpret_cast<uint32_t*>(&h1);
            } else {
                float* C = (float*)Cout;
                float2 rx0 = *reinterpret_cast<const float2*>(resid + (size_t)r0 * ldc + col);
                float2 rx1 = *reinterpret_cast<const float2*>(resid + (size_t)(r0 + 8) * ldc + col);
                float2 v0 = make_float2(acc[mf][nf][0] + b0 + rx0.x, acc[mf][nf][1] + b1 + rx0.y);
                float2 v1 = make_float2(acc[mf][nf][2] + b0 + rx1.x, acc[mf][nf][3] + b1 + rx1.y);
                *reinterpret_cast<float2*>(C + (size_t)r0 * ldc + col) = v0;
                *reinterpret_cast<float2*>(C + (size_t)(r0 + 8) * ldc + col) = v1;
            }
        }
    }
#undef LOAD_A_
#undef LOAD_B_
#undef LOAD_FRAGS_
}

// ---------------- kernel 4: 3-tap local attention (warp per token x head-pair, fp16 qkv) ----------------
__global__ __launch_bounds__(256) void local_attn_kernel() {
    int gw = (blockIdx.x * 256 + threadIdx.x) >> 5;      // KBT_*6 warps
    int lid = threadIdx.x & 31;
    int token = gw / 6;
    int hp = gw - token * 6;
    int t = token & (KT_ - 1);
    size_t base = (size_t)token * KNQKV_ + hp * 128 + lid * 4;  // q at +0, k +768, v +1536

    uint2 qu = *reinterpret_cast<const uint2*>(&g_qkvh[base]);
    float2 q01 = __half22float2(*reinterpret_cast<__half2*>(&qu.x));
    float2 q23 = __half22float2(*reinterpret_cast<__half2*>(&qu.y));

    float sc[3];
#pragma unroll
    for (int j = 0; j < 3; j++) {
        int off = (j - 1) * KINT_;
        bool valid = ((unsigned)(t + off) < (unsigned)KT_);
        float p = 0.f;
        if (valid) {
            uint2 ku = *reinterpret_cast<const uint2*>(
                &g_qkvh[base + (long long)off * KNQKV_ + 768]);
            float2 k01 = __half22float2(*reinterpret_cast<__half2*>(&ku.x));
            float2 k23 = __half22float2(*reinterpret_cast<__half2*>(&ku.y));
            p = q01.x * k01.x + q01.y * k01.y + q23.x * k23.x + q23.y * k23.y;
        }
#pragma unroll
        for (int m = 8; m; m >>= 1) p += __shfl_xor_sync(0xffffffffu, p, m);
        sc[j] = valid ? p * 0.125f : -INFINITY;          // 1/sqrt(64)
    }
    float mx = fmaxf(sc[0], fmaxf(sc[1], sc[2]));
    float e[3], den = 0.f;
#pragma unroll
    for (int j = 0; j < 3; j++) { e[j] = __expf(sc[j] - mx); den += e[j]; }
    float rden = 1.f / den;

    float a0 = 0.f, a1 = 0.f, a2 = 0.f, a3 = 0.f;
#pragma unroll
    for (int j = 0; j < 3; j++) {
        int off = (j - 1) * KINT_;
        if ((unsigned)(t + off) < (unsigned)KT_) {
            uint2 vu = *reinterpret_cast<const uint2*>(
                &g_qkvh[base + (long long)off * KNQKV_ + 1536]);
            float2 v01 = __half22float2(*reinterpret_cast<__half2*>(&vu.x));
            float2 v23 = __half22float2(*reinterpret_cast<__half2*>(&vu.y));
            float w = e[j] * rden;
            a0 += w * v01.x; a1 += w * v01.y; a2 += w * v23.x; a3 += w * v23.y;
        }
    }
    __half2 p0 = __floats2half2_rn(a0, a1);
    __half2 p1 = __floats2half2_rn(a2, a3);
    uint2 out;
    out.x = *reinterpret_cast<uint32_t*>(&p0);
    out.y = *reinterpret_cast<uint32_t*>(&p1);
    size_t base2 = (size_t)token * KD_ + hp * 128 + lid * 4;
    *reinterpret_cast<uint2*>(&g_ah[base2]) = out;
}

// ---------------- kernel 5: LayerNorm over precomputed y ----------------
__global__ __launch_bounds__(256) void ln_kernel(
    const float* __restrict__ gamma, const float* __restrict__ beta,
    float* __restrict__ out) {
    __shared__ float s_sum[8], s_sq[8];
    int r = blockIdx.x, tid = threadIdx.x, wid = tid >> 5, lid = tid & 31;
    size_t base = (size_t)r * KD_;

    float y[3], s = 0.f, s2 = 0.f;
#pragma unroll
    for (int i = 0; i < 3; i++) {
        int c = tid + i * 256;
        float v = g_o[base + c];
        y[i] = v; s += v; s2 += v * v;
    }
#pragma unroll
    for (int m = 16; m; m >>= 1) {
        s  += __shfl_xor_sync(0xffffffffu, s, m);
        s2 += __shfl_xor_sync(0xffffffffu, s2, m);
    }
    if (lid == 0) { s_sum[wid] = s; s_sq[wid] = s2; }
    __syncthreads();
    float ts = 0.f, ts2 = 0.f;
#pragma unroll
    for (int i = 0; i < 8; i++) { ts += s_sum[i]; ts2 += s_sq[i]; }
    float mean = ts * (1.f / KD_);
    float var  = ts2 * (1.f / KD_) - mean * mean;
    float inv  = rsqrtf(var + 1e-5f);
#pragma unroll
    for (int i = 0; i < 3; i++) {
        int c = tid + i * 256;
        out[base + c] = (y[i] - mean) * inv * gamma[c] + beta[c];
    }
}

// ---------------- launch ----------------
extern "C" void kernel_launch(void* const* d_in, const int* in_sizes, int n_in,
                              void* d_out, int out_size) {
    const float* x     = (const float*)d_in[0];
    const float* Wq    = (const float*)d_in[1];
    const float* bq    = (const float*)d_in[2];
    const float* Wk    = (const float*)d_in[3];
    const float* bk    = (const float*)d_in[4];
    const float* Wv    = (const float*)d_in[5];
    const float* bv    = (const float*)d_in[6];
    const float* Wo    = (const float*)d_in[7];
    const float* bo    = (const float*)d_in[8];
    const float* gamma = (const float*)d_in[9];
    const float* beta  = (const float*)d_in[10];

    void *p_ah, *p_wqkv, *p_wo, *p_qkvh, *p_o, *p_bqkv;
    cudaGetSymbolAddress(&p_ah,   g_ah);
    cudaGetSymbolAddress(&p_wqkv, g_wqkv);
    cudaGetSymbolAddress(&p_wo,   g_wo);
    cudaGetSymbolAddress(&p_qkvh, g_qkvh);
    cudaGetSymbolAddress(&p_o,    g_o);
    cudaGetSymbolAddress(&p_bqkv, g_bqkv);

    const __half* ah   = (const __half*)p_ah;
    const __half* wqkv = (const __half*)p_wqkv;
    const __half* wo   = (const __half*)p_wo;

    cudaFuncSetAttribute(gemm_kernel<true>,
                         cudaFuncAttributeMaxDynamicSharedMemorySize, (int)SMEM_BYTES_);
    cudaFuncSetAttribute(gemm_kernel<false>,
                         cudaFuncAttributeMaxDynamicSharedMemorySize, (int)SMEM_BYTES_);

    prep_weights_kernel<<<WELEM_ / 256, 256>>>(Wq, Wk, Wv, Wo, bq, bk, bv);
    split_x_kernel<<<(int)(KNELEM_ / 4 / 256), 256>>>(x);

    // fused QKV: C[32768, 2304] fp16
    dim3 gqkv(KNQKV_ / BN_, KBT_ / BM_);   // (18, 256)
    gemm_kernel<true><<<gqkv, 256, SMEM_BYTES_>>>(ah, wqkv, (const float*)p_bqkv,
                                                  p_qkvh, KNQKV_, nullptr);
    // attention: 32768 tokens * 6 head-pairs = 196608 warps = 24576 blocks
    local_attn_kernel<<<KBT_ * 6 / 8, 256>>>();
    // O projection: C[32768, 768] fp32 with fused residual (y = o + bo + x)
    dim3 go(KD_ / BN_, KBT_ / BM_);        // (6, 256)
    gemm_kernel<false><<<go, 256, SMEM_BYTES_>>>(ah, wo, bo, p_o, KD_, x);
    ln_kernel<<<KBT_, 256>>>(gamma, beta, (float*)d_out);
}

// round 17
// speedup vs baseline: 2.3761x; 1.0229x over previous
#include <cuda_runtime.h>
#include <cuda_fp16.h>
#include <cstdint>
#include <math.h>

// ---------------- problem constants ----------------
#define KB_   8
#define KT_   4096
#define KD_   768
#define KH_   12
#define KHD_  64
#define KINT_ 3
#define KBT_  (KB_ * KT_)                 // 32768
#define KNELEM_ ((size_t)KBT_ * KD_)      // 25165824
#define KNQKV_ 2304                       // Wq|Wk|Wv stacked along N
#define WELEM_ (KD_ * KD_)

// GEMM tiling: 128x128 CTA, 4 warps of 64x64, 3 stages -> 2 CTAs/SM
#define BM_ 128
#define BN_ 128
#define BK_ 64
#define KITERS_ 12                        // single-term fp16: K=768 = 12 x 64
#define STAGES_ 3
#define STAGE_BYTES_ 32768u               // A 16KB + B 16KB
#define OFF_B_ 16384u
#define SMEM_BYTES_ (STAGES_ * STAGE_BYTES_)   // 98304
#define GTHREADS_ 128

// ---------------- device scratch ----------------
__device__ __half g_ah[KNELEM_];                             // fp16 activations (x, then attn)
__device__ __half g_wqkv[(size_t)KNQKV_ * KD_];              // fp16 [Wq;Wk;Wv]^T rows [n][k]
__device__ __half g_wo[(size_t)KD_ * KD_];                   // fp16 Wo^T [n][k]
__device__ float g_bqkv[KNQKV_];                             // concat bias q|k|v
__device__ __half g_qkvh[(size_t)KBT_ * KNQKV_];             // fused QKV output (fp16)
__device__ float g_o[KNELEM_];                               // y = o + bias + residual

// ---------------- helpers ----------------
__device__ __forceinline__ uint32_t smem_u32(const void* p) {
    return (uint32_t)__cvta_generic_to_shared(p);
}

__device__ __forceinline__ void cp_async16(uint32_t saddr, const void* gaddr) {
    asm volatile("cp.async.cg.shared.global [%0], [%1], 16;" :: "r"(saddr), "l"(gaddr));
}
#define CP_COMMIT_()  asm volatile("cp.async.commit_group;" ::: "memory")
#define CP_WAIT_(n)   asm volatile("cp.async.wait_group %0;" :: "n"(n) : "memory")

__device__ __forceinline__ void ldsm_x4(uint32_t& r0, uint32_t& r1, uint32_t& r2, uint32_t& r3,
                                        uint32_t addr) {
    asm volatile("ldmatrix.sync.aligned.m8n8.x4.shared.b16 {%0,%1,%2,%3}, [%4];"
                 : "=r"(r0), "=r"(r1), "=r"(r2), "=r"(r3) : "r"(addr));
}

__device__ __forceinline__ void mma_f16(float* c, const uint32_t* a, const uint32_t* b) {
    asm volatile(
        "mma.sync.aligned.m16n8k16.row.col.f32.f16.f16.f32 "
        "{%0,%1,%2,%3}, {%4,%5,%6,%7}, {%8,%9}, {%0,%1,%2,%3};"
        : "+f"(c[0]), "+f"(c[1]), "+f"(c[2]), "+f"(c[3])
        : "r"(a[0]), "r"(a[1]), "r"(a[2]), "r"(a[3]), "r"(b[0]), "r"(b[1]));
}

// ---------------- kernel 1: transpose weights -> fp16, concat bias ----------------
__global__ __launch_bounds__(256) void prep_weights_kernel(
    const float* __restrict__ Wq, const float* __restrict__ Wk,
    const float* __restrict__ Wv, const float* __restrict__ Wo,
    const float* __restrict__ bq, const float* __restrict__ bk,
    const float* __restrict__ bv) {
    int idx = blockIdx.x * 256 + threadIdx.x;       // over D*D
    int n = idx / KD_;
    int k = idx - n * KD_;
    g_wqkv[(size_t)n * KD_ + k]          = __float2half(Wq[(size_t)k * KD_ + n]);
    g_wqkv[(size_t)(768 + n) * KD_ + k]  = __float2half(Wk[(size_t)k * KD_ + n]);
    g_wqkv[(size_t)(1536 + n) * KD_ + k] = __float2half(Wv[(size_t)k * KD_ + n]);
    g_wo[(size_t)n * KD_ + k]            = __float2half(Wo[(size_t)k * KD_ + n]);
    if (idx < KNQKV_) {
        g_bqkv[idx] = (idx < 768) ? bq[idx] : (idx < 1536) ? bk[idx - 768] : bv[idx - 1536];
    }
}

// ---------------- kernel 2: convert x -> fp16 ----------------
__global__ __launch_bounds__(256) void split_x_kernel(const float* __restrict__ x) {
    long long gid = (long long)blockIdx.x * 256 + threadIdx.x;   // over KNELEM/4
    long long i = gid * 4;
    float4 v = *reinterpret_cast<const float4*>(x + i);
    __half2 p0 = __floats2half2_rn(v.x, v.y);
    __half2 p1 = __floats2half2_rn(v.z, v.w);
    uint2 out;
    out.x = *reinterpret_cast<uint32_t*>(&p0);
    out.y = *reinterpret_cast<uint32_t*>(&p1);
    *reinterpret_cast<uint2*>(&g_ah[i]) = out;
}

// ---------------- kernel 3: pipelined fp16 mma.sync GEMM (4 warps, 64x64 warp tile) ----------------
// C[M, ldc] = A[M,768] * B[ldc,768]^T + bias ; HALF_OUT: fp16 store, else fp32 + residual
template <bool HALF_OUT>
__global__ __launch_bounds__(GTHREADS_, 2) void gemm_kernel(
    const __half* __restrict__ A, const __half* __restrict__ B,
    const float* __restrict__ bias, void* __restrict__ Cout, int ldc,
    const float* __restrict__ resid) {
    extern __shared__ char smem[];
    const uint32_t sb = smem_u32(smem);
    const int tid = threadIdx.x, lane = tid & 31, wid = tid >> 5;   // 4 warps
    const int m0 = blockIdx.y * BM_;
    const int n0 = blockIdx.x * BN_;
    const int wm = (wid >> 1) * 64;     // 2 m-warps x 64
    const int wn = (wid & 1) * 64;      // 2 n-warps x 64

    const int arow = tid >> 3, acg = tid & 7;        // 16 rows x 8 chunk-cols per pass
    const __half* Abase = A + (size_t)m0 * KD_;
    const __half* Bbase = B + (size_t)n0 * KD_;

    // ldmatrix lane constants
    const int a_row_l = wm + (lane & 15);
    const uint32_t a_xor = (uint32_t)(a_row_l & 7) << 4;
    const uint32_t a_k2 = (uint32_t)(lane >> 4) * 16;
    const int gq = lane >> 3;
    const int b_row_l = wn + (gq >> 1) * 8 + (lane & 7);
    const uint32_t b_xor = (uint32_t)(b_row_l & 7) << 4;
    const uint32_t b_k2 = (uint32_t)(gq & 1) * 16;

    float acc[4][8][4];
#pragma unroll
    for (int i = 0; i < 4; i++)
#pragma unroll
        for (int j = 0; j < 8; j++)
#pragma unroll
            for (int r = 0; r < 4; r++) acc[i][j][r] = 0.f;

#define LOAD_A_(st_, kc_)                                                           \
    {                                                                               \
        int k0_ = (kc_) * BK_;                                                      \
        _Pragma("unroll")                                                           \
        for (int it_ = 0; it_ < 8; it_++) {                                         \
            int row_ = arow + it_ * 16;                                             \
            uint32_t so_ = (st_) + (uint32_t)row_ * 128 +                           \
                           (((uint32_t)acg * 16) ^ ((uint32_t)(row_ & 7) << 4));    \
            cp_async16(so_, Abase + (size_t)row_ * KD_ + k0_ + acg * 8);            \
        }                                                                           \
    }
#define LOAD_B_(st_, kc_)                                                           \
    {                                                                               \
        int k0_ = (kc_) * BK_;                                                      \
        _Pragma("unroll")                                                           \
        for (int it_ = 0; it_ < 8; it_++) {                                         \
            int row_ = arow + it_ * 16;                                             \
            uint32_t so_ = (st_) + OFF_B_ + (uint32_t)row_ * 128 +                  \
                           (((uint32_t)acg * 16) ^ ((uint32_t)(row_ & 7) << 4));    \
            cp_async16(so_, Bbase + (size_t)row_ * KD_ + k0_ + acg * 8);            \
        }                                                                           \
    }

    // prologue: stages 0..1
    LOAD_A_(sb, 0); LOAD_B_(sb, 0); CP_COMMIT_();
    LOAD_A_(sb + STAGE_BYTES_, 1); LOAD_B_(sb + STAGE_BYTES_, 1); CP_COMMIT_();

    uint32_t Af[2][4][4], Bf[2][8][2];

#define LOAD_FRAGS_(st, ks, buf)                                                    \
    {                                                                               \
        _Pragma("unroll")                                                           \
        for (int mf_ = 0; mf_ < 4; mf_++) {                                         \
            uint32_t ad_ = (st) + (uint32_t)(a_row_l + mf_ * 16) * 128 +            \
                           (((uint32_t)((ks) * 32) + a_k2) ^ a_xor);                \
            ldsm_x4(Af[buf][mf_][0], Af[buf][mf_][1], Af[buf][mf_][2],              \
                    Af[buf][mf_][3], ad_);                                          \
        }                                                                           \
        _Pragma("unroll")                                                           \
        for (int np_ = 0; np_ < 4; np_++) {                                         \
            uint32_t bd_ = (st) + OFF_B_ + (uint32_t)(b_row_l + np_ * 16) * 128 +   \
                           (((uint32_t)((ks) * 32) + b_k2) ^ b_xor);                \
            uint32_t r0_, r1_, r2_, r3_;                                            \
            ldsm_x4(r0_, r1_, r2_, r3_, bd_);                                       \
            Bf[buf][np_ * 2][0] = r0_; Bf[buf][np_ * 2][1] = r1_;                   \
            Bf[buf][np_ * 2 + 1][0] = r2_; Bf[buf][np_ * 2 + 1][1] = r3_;           \
        }                                                                           \
    }

    // wait stage 0, preload its ks0 fragments
    CP_WAIT_(1);
    __syncthreads();
    LOAD_FRAGS_(sb, 0, 0);

    const uint32_t stage_off[3] = {0u, STAGE_BYTES_, 2u * STAGE_BYTES_};
    int cur = 0;                 // stage index of kc
    for (int kc = 0; kc < KITERS_; kc++) {
        const uint32_t st = sb + stage_off[cur];
        int ldstage = cur + 2; if (ldstage >= 3) ldstage -= 3;
        const uint32_t lst = sb + stage_off[ldstage];
        int nxt = cur + 1; if (nxt >= 3) nxt -= 3;
        const int ld = kc + 2;
        const bool doload = ld < KITERS_;
#pragma unroll
        for (int ks = 0; ks < 4; ks++) {
            if (ks == 0 && doload) { LOAD_A_(lst, ld); }
            if (ks == 1 && doload) { LOAD_B_(lst, ld); }
            if (ks == 1) { CP_COMMIT_(); }
            if (ks == 3) {
                if (kc + 1 < KITERS_) {
                    CP_WAIT_(1);
                    __syncthreads();
                    LOAD_FRAGS_(sb + stage_off[nxt], 0, 0);
                }
            } else {
                LOAD_FRAGS_(st, ks + 1, (ks + 1) & 1);
            }
#pragma unroll
            for (int mf = 0; mf < 4; mf++)
#pragma unroll
                for (int nf = 0; nf < 8; nf++)
                    mma_f16(acc[mf][nf], Af[ks & 1][mf], Bf[ks & 1][nf]);
        }
        cur = nxt;
    }

    // epilogue
    const int crow0 = m0 + wm + (lane >> 2);
    const int ccol0 = n0 + wn + (lane & 3) * 2;
#pragma unroll
    for (int mf = 0; mf < 4; mf++) {
#pragma unroll
        for (int nf = 0; nf < 8; nf++) {
            int col = ccol0 + nf * 8;
            float b0 = bias[col], b1 = bias[col + 1];
            int r0 = crow0 + mf * 16;
            if (HALF_OUT) {
                __half* C = (__half*)Cout;
                __half2 h0 = __floats2half2_rn(acc[mf][nf][0] + b0, acc[mf][nf][1] + b1);
                __half2 h1 = __floats2half2_rn(acc[mf][nf][2] + b0, acc[mf][nf][3] + b1);
                *reinterpret_cast<uint32_t*>(C + (size_t)r0 * ldc + col) =
                    *reinterpret_cast<uint32_t*>(&h0);
                *reinterpret_cast<uint32_t*>(C + (size_t)(r0 + 8) * ldc + col) =
                    *reinterpret_cast<uint32_t*>(&h1);
            } else {
                float* C = (float*)Cout;
                float2 rx0 = *reinterpret_cast<const float2*>(resid + (size_t)r0 * ldc + col);
                float2 rx1 = *reinterpret_cast<const float2*>(resid + (size_t)(r0 + 8) * ldc + col);
                float2 v0 = make_float2(acc[mf][nf][0] + b0 + rx0.x, acc[mf][nf][1] + b1 + rx0.y);
                float2 v1 = make_float2(acc[mf][nf][2] + b0 + rx1.x, acc[mf][nf][3] + b1 + rx1.y);
                *reinterpret_cast<float2*>(C + (size_t)r0 * ldc + col) = v0;
                *reinterpret_cast<float2*>(C + (size_t)(r0 + 8) * ldc + col) = v1;
            }
        }
    }
#undef LOAD_A_
#undef LOAD_B_
#undef LOAD_FRAGS_
}

// ---------------- kernel 4: 3-tap local attention (warp per token x head-pair, fp16 qkv) ----------------
__global__ __launch_bounds__(256) void local_attn_kernel() {
    int gw = (blockIdx.x * 256 + threadIdx.x) >> 5;      // KBT_*6 warps
    int lid = threadIdx.x & 31;
    int token = gw / 6;
    int hp = gw - token * 6;
    int t = token & (KT_ - 1);
    size_t base = (size_t)token * KNQKV_ + hp * 128 + lid * 4;  // q at +0, k +768, v +1536

    uint2 qu = *reinterpret_cast<const uint2*>(&g_qkvh[base]);
    float2 q01 = __half22float2(*reinterpret_cast<__half2*>(&qu.x));
    float2 q23 = __half22float2(*reinterpret_cast<__half2*>(&qu.y));

    float sc[3];
#pragma unroll
    for (int j = 0; j < 3; j++) {
        int off = (j - 1) * KINT_;
        bool valid = ((unsigned)(t + off) < (unsigned)KT_);
        float p = 0.f;
        if (valid) {
            uint2 ku = *reinterpret_cast<const uint2*>(
                &g_qkvh[base + (long long)off * KNQKV_ + 768]);
            float2 k01 = __half22float2(*reinterpret_cast<__half2*>(&ku.x));
            float2 k23 = __half22float2(*reinterpret_cast<__half2*>(&ku.y));
            p = q01.x * k01.x + q01.y * k01.y + q23.x * k23.x + q23.y * k23.y;
        }
#pragma unroll
        for (int m = 8; m; m >>= 1) p += __shfl_xor_sync(0xffffffffu, p, m);
        sc[j] = valid ? p * 0.125f : -INFINITY;          // 1/sqrt(64)
    }
    float mx = fmaxf(sc[0], fmaxf(sc[1], sc[2]));
    float e[3], den = 0.f;
#pragma unroll
    for (int j = 0; j < 3; j++) { e[j] = __expf(sc[j] - mx); den += e[j]; }
    float rden = 1.f / den;

    float a0 = 0.f, a1 = 0.f, a2 = 0.f, a3 = 0.f;
#pragma unroll
    for (int j = 0; j < 3; j++) {
        int off = (j - 1) * KINT_;
        if ((unsigned)(t + off) < (unsigned)KT_) {
            uint2 vu = *reinterpret_cast<const uint2*>(
                &g_qkvh[base + (long long)off * KNQKV_ + 1536]);
            float2 v01 = __half22float2(*reinterpret_cast<__half2*>(&vu.x));
            float2 v23 = __half22float2(*reinterpret_cast<__half2*>(&vu.y));
            float w = e[j] * rden;
            a0 += w * v01.x; a1 += w * v01.y; a2 += w * v23.x; a3 += w * v23.y;
        }
    }
    __half2 p0 = __floats2half2_rn(a0, a1);
    __half2 p1 = __floats2half2_rn(a2, a3);
    uint2 out;
    out.x = *reinterpret_cast<uint32_t*>(&p0);
    out.y = *reinterpret_cast<uint32_t*>(&p1);
    size_t base2 = (size_t)token * KD_ + hp * 128 + lid * 4;
    *reinterpret_cast<uint2*>(&g_ah[base2]) = out;
}

// ---------------- kernel 5: LayerNorm over precomputed y ----------------
__global__ __launch_bounds__(256) void ln_kernel(
    const float* __restrict__ gamma, const float* __restrict__ beta,
    float* __restrict__ out) {
    __shared__ float s_sum[8], s_sq[8];
    int r = blockIdx.x, tid = threadIdx.x, wid = tid >> 5, lid = tid & 31;
    size_t base = (size_t)r * KD_;

    float y[3], s = 0.f, s2 = 0.f;
#pragma unroll
    for (int i = 0; i < 3; i++) {
        int c = tid + i * 256;
        float v = g_o[base + c];
        y[i] = v; s += v; s2 += v * v;
    }
#pragma unroll
    for (int m = 16; m; m >>= 1) {
        s  += __shfl_xor_sync(0xffffffffu, s, m);
        s2 += __shfl_xor_sync(0xffffffffu, s2, m);
    }
    if (lid == 0) { s_sum[wid] = s; s_sq[wid] = s2; }
    __syncthreads();
    float ts = 0.f, ts2 = 0.f;
#pragma unroll
    for (int i = 0; i < 8; i++) { ts += s_sum[i]; ts2 += s_sq[i]; }
    float mean = ts * (1.f / KD_);
    float var  = ts2 * (1.f / KD_) - mean * mean;
    float inv  = rsqrtf(var + 1e-5f);
#pragma unroll
    for (int i = 0; i < 3; i++) {
        int c = tid + i * 256;
        out[base + c] = (y[i] - mean) * inv * gamma[c] + beta[c];
    }
}

// ---------------- launch ----------------
extern "C" void kernel_launch(void* const* d_in, const int* in_sizes, int n_in,
                              void* d_out, int out_size) {
    const float* x     = (const float*)d_in[0];
    const float* Wq    = (const float*)d_in[1];
    const float* bq    = (const float*)d_in[2];
    const float* Wk    = (const float*)d_in[3];
    const float* bk    = (const float*)d_in[4];
    const float* Wv    = (const float*)d_in[5];
    const float* bv    = (const float*)d_in[6];
    const float* Wo    = (const float*)d_in[7];
    const float* bo    = (const float*)d_in[8];
    const float* gamma = (const float*)d_in[9];
    const float* beta  = (const float*)d_in[10];

    void *p_ah, *p_wqkv, *p_wo, *p_qkvh, *p_o, *p_bqkv;
    cudaGetSymbolAddress(&p_ah,   g_ah);
    cudaGetSymbolAddress(&p_wqkv, g_wqkv);
    cudaGetSymbolAddress(&p_wo,   g_wo);
    cudaGetSymbolAddress(&p_qkvh, g_qkvh);
    cudaGetSymbolAddress(&p_o,    g_o);
    cudaGetSymbolAddress(&p_bqkv, g_bqkv);

    const __half* ah   = (const __half*)p_ah;
    const __half* wqkv = (const __half*)p_wqkv;
    const __half* wo   = (const __half*)p_wo;

    cudaFuncSetAttribute(gemm_kernel<true>,
                         cudaFuncAttributeMaxDynamicSharedMemorySize, (int)SMEM_BYTES_);
    cudaFuncSetAttribute(gemm_kernel<false>,
                         cudaFuncAttributeMaxDynamicSharedMemorySize, (int)SMEM_BYTES_);

    prep_weights_kernel<<<WELEM_ / 256, 256>>>(Wq, Wk, Wv, Wo, bq, bk, bv);
    split_x_kernel<<<(int)(KNELEM_ / 4 / 256), 256>>>(x);

    // fused QKV: C[32768, 2304] fp16
    dim3 gqkv(KNQKV_ / BN_, KBT_ / BM_);   // (18, 256)
    gemm_kernel<true><<<gqkv, GTHREADS_, SMEM_BYTES_>>>(ah, wqkv, (const float*)p_bqkv,
                                                        p_qkvh, KNQKV_, nullptr);
    // attention: 32768 tokens * 6 head-pairs = 196608 warps = 24576 blocks
    local_attn_kernel<<<KBT_ * 6 / 8, 256>>>();
    // O projection: C[32768, 768] fp32 with fused residual (y = o + bo + x)
    dim3 go(KD_ / BN_, KBT_ / BM_);        // (6, 256)
    gemm_kernel<false><<<go, GTHREADS_, SMEM_BYTES_>>>(ah, wo, bo, p_o, KD_, x);
    ln_kernel<<<KBT_, 256>>>(gamma, beta, (float*)d_out);
}